// round 2
// baseline (speedup 1.0000x reference)
#include <cuda_runtime.h>
#include <math.h>

#define SEQ 256
#define WE 100
#define TE 20
#define INDIM 120
#define H 400
#define G4 1600
#define M 200
#define MC 50
#define NCHUNK 4
#define TABROWS 257
#define N_ARC 65536
#define N_SIB 200000
#define N_GP 200000
#define N_GSIB 300000
#define OUT_TOTAL (N_ARC + N_SIB + N_GP + N_GSIB)

// ---------------- device scratch (no allocations allowed) ----------------
__device__ float g_zin[2][SEQ][G4];          // precomputed input gate contributions
__device__ float g_states[SEQ][2 * H];       // BiLSTM outputs [seq, 2H]
__device__ float g_tab[12][TABROWS][M];      // projection tables (+ null row at 256)
__device__ float g_h[2][2][H];               // double-buffered h per direction
__device__ unsigned int g_bar[2];            // per-direction step barriers

// ---------------- kernel 0: zero output + reset barriers ----------------
__global__ void setup_kernel(float* __restrict__ out, int n) {
    int i = blockIdx.x * blockDim.x + threadIdx.x;
    if (i < n) out[i] = 0.f;
    if (i < 2) g_bar[i] = 0u;
}

// ---------------- kernel 1: embeddings + z_in = xs @ Wih.T + b ----------------
__global__ void __launch_bounds__(256) zin_kernel(
    const int* __restrict__ words, const int* __restrict__ tags,
    const float* __restrict__ word_emb, const float* __restrict__ tag_emb,
    const float* __restrict__ Wih_f, const float* __restrict__ b_f,
    const float* __restrict__ Wih_b, const float* __restrict__ b_b)
{
    __shared__ __align__(16) float xs[2][4][INDIM];
    int tid = threadIdx.x;
    int s_base = blockIdx.x * 4;

    for (int i = tid; i < 2 * 4 * INDIM; i += 256) {
        int dirr = i / (4 * INDIM);
        int jj = (i / INDIM) & 3;
        int k = i % INDIM;
        int s = s_base + jj;
        int pos = dirr ? (SEQ - 1 - s) : s;  // backward LSTM consumes reversed x
        float v = (k < WE) ? word_emb[words[pos] * WE + k]
                           : tag_emb[tags[pos] * TE + (k - WE)];
        xs[dirr][jj][k] = v;
    }
    __syncthreads();

    for (int o = tid; o < 2 * G4; o += 256) {
        int dirr = o / G4;
        int row = o - dirr * G4;
        const float* Wp = dirr ? Wih_b : Wih_f;
        float bias = (dirr ? b_b : b_f)[row];
        const float4* wr = (const float4*)(Wp + row * INDIM);
        float a0 = 0.f, a1 = 0.f, a2 = 0.f, a3 = 0.f;
        #pragma unroll
        for (int k = 0; k < INDIM / 4; k++) {
            float4 w = __ldg(wr + k);
            const float* x0 = &xs[dirr][0][k * 4];
            const float* x1 = &xs[dirr][1][k * 4];
            const float* x2 = &xs[dirr][2][k * 4];
            const float* x3 = &xs[dirr][3][k * 4];
            a0 += w.x * x0[0] + w.y * x0[1] + w.z * x0[2] + w.w * x0[3];
            a1 += w.x * x1[0] + w.y * x1[1] + w.z * x1[2] + w.w * x1[3];
            a2 += w.x * x2[0] + w.y * x2[1] + w.z * x2[2] + w.w * x2[3];
            a3 += w.x * x3[0] + w.y * x3[1] + w.z * x3[2] + w.w * x3[3];
        }
        g_zin[dirr][s_base + 0][row] = a0 + bias;
        g_zin[dirr][s_base + 1][row] = a1 + bias;
        g_zin[dirr][s_base + 2][row] = a2 + bias;
        g_zin[dirr][s_base + 3][row] = a3 + bias;
    }
}

// ---------------- kernel 2: BiLSTM scan, 16 CTAs per direction ----------------
// CTA owns 25 h-indices -> 100 Whh rows (160KB, L1-resident via __ldg).
// Per step: dot products, gate update, global spin barrier, h exchange (.cg).
__global__ void __launch_bounds__(512) lstm_kernel(
    const float* __restrict__ Whh_f, const float* __restrict__ Whh_b)
{
    int dir = blockIdx.x >> 4;
    int slice = blockIdx.x & 15;
    int j0 = slice * 25;
    const float* Whh = dir ? Whh_b : Whh_f;

    __shared__ __align__(16) float h_sm[H];
    __shared__ float z_sm[100];
    __shared__ float c_sm[25];

    int tid = threadIdx.x;
    int r = tid >> 2, q = tid & 3;
    int rr = (r < 100) ? r : 99;               // clamp padding threads
    int gate = rr / 25, jj = rr % 25;
    int row = gate * 400 + j0 + jj;
    const float4* wrow = (const float4*)(Whh + row * H + q * 100);

    if (tid < H) h_sm[tid] = 0.f;
    if (tid < 25) c_sm[tid] = 0.f;
    __syncthreads();

    unsigned int target = 16;
    for (int step = 0; step < SEQ; step++) {
        // partial dot: 100 k-values per thread (float4)
        float acc = 0.f;
        const float4* hp = (const float4*)(h_sm + q * 100);
        #pragma unroll
        for (int k = 0; k < 25; k++) {
            float4 w = __ldg(wrow + k);
            float4 h4 = hp[k];
            acc += w.x * h4.x + w.y * h4.y + w.z * h4.z + w.w * h4.w;
        }
        acc += __shfl_down_sync(0xffffffffu, acc, 2, 4);
        acc += __shfl_down_sync(0xffffffffu, acc, 1, 4);
        if (q == 0 && r < 100) z_sm[r] = acc;
        __syncthreads();

        if (tid < 25) {
            const float* zin = &g_zin[dir][step][0];
            float zi = z_sm[tid]      + zin[0 * H + j0 + tid];
            float zf = z_sm[25 + tid] + zin[1 * H + j0 + tid];
            float zg = z_sm[50 + tid] + zin[2 * H + j0 + tid];
            float zo = z_sm[75 + tid] + zin[3 * H + j0 + tid];
            float ig = 1.f / (1.f + expf(-zi));
            float fg = 1.f / (1.f + expf(-zf));
            float og = 1.f / (1.f + expf(-zo));
            float gg = tanhf(zg);
            float c = fg * c_sm[tid] + ig * gg;
            c_sm[tid] = c;
            float h = og * tanhf(c);
            int par = (step + 1) & 1;
            __stcg(&g_h[par][dir][j0 + tid], h);
            int tpos = dir ? (SEQ - 1 - step) : step;
            g_states[tpos][dir * H + j0 + tid] = h;
        }
        __threadfence();
        __syncthreads();
        if (tid == 0) {
            atomicAdd(&g_bar[dir], 1u);
            while (*(volatile unsigned int*)&g_bar[dir] < target) { }
            __threadfence();
        }
        __syncthreads();
        target += 16;
        if (step < SEQ - 1) {
            if (tid < H) h_sm[tid] = __ldcg(&g_h[(step + 1) & 1][dir][tid]);
            __syncthreads();
        }
    }
}

// ---------------- kernel 3: proj[p,s,m] = W_proj[p,m,:] . states[s,:] ----------------
__global__ void __launch_bounds__(256) proj_kernel(
    const float* __restrict__ W_proj, const float* __restrict__ null_sib)
{
    int p = blockIdx.x;       // 0..11
    int s0 = blockIdx.y * 8;  // 8 sequence rows per block
    __shared__ __align__(16) float st[8][2 * H];
    int tid = threadIdx.x;
    for (int i = tid; i < 8 * 2 * H; i += 256)
        st[i / (2 * H)][i % (2 * H)] = g_states[s0 + i / (2 * H)][i % (2 * H)];
    __syncthreads();

    if (tid < M) {
        float acc[8];
        #pragma unroll
        for (int s = 0; s < 8; s++) acc[s] = 0.f;
        const float4* w = (const float4*)(W_proj + ((size_t)p * M + tid) * 2 * H);
        for (int k = 0; k < (2 * H) / 4; k++) {
            float4 wv = __ldg(w + k);
            #pragma unroll
            for (int s = 0; s < 8; s++) {
                float4 sv = *(const float4*)&st[s][k * 4];
                acc[s] += wv.x * sv.x + wv.y * sv.y + wv.z * sv.z + wv.w * sv.w;
            }
        }
        #pragma unroll
        for (int s = 0; s < 8; s++)
            g_tab[p][s0 + s][tid] = acc[s];
        if ((p == 7 || p == 10) && blockIdx.y == 0)
            g_tab[p][256][tid] = null_sib[tid];   // null_sib row for sib tables
    }
}

// ---------------- kernel 4: scoring, smem-staged tables, warp-per-tuple ----------------
template <int T>
__global__ void __launch_bounds__(256) score_kernel(
    int p0, int p1, int p2, int p3,
    const int* __restrict__ i0, const int* __restrict__ i1,
    const int* __restrict__ i2, const int* __restrict__ i3,
    const float* __restrict__ ws, float* __restrict__ out, int N)
{
    extern __shared__ float smem[];
    const int m0 = blockIdx.x * MC;

    // stage table m-chunks into shared memory
    int pp[4] = {p0, p1, p2, p3};
    int total = T * TABROWS * MC;
    for (int i = threadIdx.x; i < total; i += blockDim.x) {
        int t = i / (TABROWS * MC);
        int rem = i - t * (TABROWS * MC);
        int s = rem / MC, mm = rem - s * MC;
        smem[i] = g_tab[pp[t]][s][m0 + mm];
    }
    int lane = threadIdx.x & 31;
    float ws0 = ws[m0 + lane];
    float ws1 = (lane < MC - 32) ? ws[m0 + 32 + lane] : 0.f;
    __syncthreads();

    const float* T0 = smem;
    const float* T1 = smem + TABROWS * MC;
    const float* T2 = smem + 2 * TABROWS * MC;
    const float* T3 = smem + 3 * TABROWS * MC;

    int wid = threadIdx.x >> 5;
    int gw = blockIdx.y * (blockDim.x >> 5) + wid;
    int nw = gridDim.y * (blockDim.x >> 5);

    for (int base = gw * 32; base < N; base += nw * 32) {
        int n = min(32, N - base);
        int a0 = 0, a1 = 0, a2 = 0, a3 = 0;
        if (lane < n) {
            a0 = i0[base + lane];
            a1 = i1[base + lane];
            if (T > 2) a2 = i2[base + lane];
            if (T > 3) a3 = i3[base + lane];
        }
        for (int j = 0; j < n; j++) {
            int h  = __shfl_sync(0xffffffffu, a0, j);
            int mo = __shfl_sync(0xffffffffu, a1, j);
            int si = (T > 2) ? __shfl_sync(0xffffffffu, a2, j) : 0;
            int gr = (T > 3) ? __shfl_sync(0xffffffffu, a3, j) : 0;

            float v = T0[h * MC + lane] + T1[mo * MC + lane];
            if (T > 2) v += T2[si * MC + lane];
            if (T > 3) v += T3[gr * MC + lane];
            float acc = ws0 * tanhf(v);
            if (lane < MC - 32) {
                float v1 = T0[h * MC + 32 + lane] + T1[mo * MC + 32 + lane];
                if (T > 2) v1 += T2[si * MC + 32 + lane];
                if (T > 3) v1 += T3[gr * MC + 32 + lane];
                acc += ws1 * tanhf(v1);
            }
            #pragma unroll
            for (int off = 16; off; off >>= 1)
                acc += __shfl_xor_sync(0xffffffffu, acc, off);
            if (lane == 0) atomicAdd(&out[base + j], acc);
        }
    }
}

// ---------------- host launcher ----------------
extern "C" void kernel_launch(void* const* d_in, const int* in_sizes, int n_in,
                              void* d_out, int out_size)
{
    const int* words      = (const int*)d_in[0];
    const int* tags       = (const int*)d_in[1];
    const int* arc_head   = (const int*)d_in[2];
    const int* arc_mod    = (const int*)d_in[3];
    const int* sib_head   = (const int*)d_in[4];
    const int* sib_mod    = (const int*)d_in[5];
    const int* sib_sib    = (const int*)d_in[6];
    const int* gp_head    = (const int*)d_in[7];
    const int* gp_mod     = (const int*)d_in[8];
    const int* gp_grand   = (const int*)d_in[9];
    const int* gsib_head  = (const int*)d_in[10];
    const int* gsib_mod   = (const int*)d_in[11];
    const int* gsib_sib   = (const int*)d_in[12];
    const int* gsib_grand = (const int*)d_in[13];
    const float* word_emb = (const float*)d_in[14];
    const float* tag_emb  = (const float*)d_in[15];
    const float* Wih_f    = (const float*)d_in[16];
    const float* Whh_f    = (const float*)d_in[17];
    const float* b_f      = (const float*)d_in[18];
    const float* Wih_b    = (const float*)d_in[19];
    const float* Whh_b    = (const float*)d_in[20];
    const float* b_b      = (const float*)d_in[21];
    const float* W_proj   = (const float*)d_in[22];
    const float* W_score  = (const float*)d_in[23];
    const float* null_sib = (const float*)d_in[24];
    float* out = (float*)d_out;

    // opt-in dynamic smem for scoring kernels (idempotent, non-stream API)
    cudaFuncSetAttribute(score_kernel<2>, cudaFuncAttributeMaxDynamicSharedMemorySize,
                         2 * TABROWS * MC * (int)sizeof(float));
    cudaFuncSetAttribute(score_kernel<3>, cudaFuncAttributeMaxDynamicSharedMemorySize,
                         3 * TABROWS * MC * (int)sizeof(float));
    cudaFuncSetAttribute(score_kernel<4>, cudaFuncAttributeMaxDynamicSharedMemorySize,
                         4 * TABROWS * MC * (int)sizeof(float));

    setup_kernel<<<(OUT_TOTAL + 511) / 512, 512>>>(out, OUT_TOTAL);
    zin_kernel<<<SEQ / 4, 256>>>(words, tags, word_emb, tag_emb,
                                 Wih_f, b_f, Wih_b, b_b);
    lstm_kernel<<<32, 512>>>(Whh_f, Whh_b);
    proj_kernel<<<dim3(12, 32), 256>>>(W_proj, null_sib);

    dim3 sgrid(NCHUNK, 37);
    score_kernel<2><<<sgrid, 256, 2 * TABROWS * MC * sizeof(float)>>>(
        0, 1, 0, 0, arc_head, arc_mod, nullptr, nullptr,
        W_score + 0 * M, out, N_ARC);
    score_kernel<3><<<sgrid, 256, 3 * TABROWS * MC * sizeof(float)>>>(
        5, 6, 7, 0, sib_head, sib_mod, sib_sib, nullptr,
        W_score + 1 * M, out + N_ARC, N_SIB);
    score_kernel<3><<<sgrid, 256, 3 * TABROWS * MC * sizeof(float)>>>(
        3, 4, 2, 0, gp_head, gp_mod, gp_grand, nullptr,
        W_score + 2 * M, out + N_ARC + N_SIB, N_GP);
    score_kernel<4><<<sgrid, 256, 4 * TABROWS * MC * sizeof(float)>>>(
        8, 9, 10, 11, gsib_head, gsib_mod, gsib_sib, gsib_grand,
        W_score + 3 * M, out + N_ARC + N_SIB + N_GP, N_GSIB);
}

// round 3
// speedup vs baseline: 1.7858x; 1.7858x over previous
#include <cuda_runtime.h>
#include <math.h>

#define SEQ 256
#define WE 100
#define TE 20
#define INDIM 120
#define H 400
#define G4 1600
#define M 200
#define MC 50
#define NCHUNK 4
#define TABROWS 257
#define N_ARC 65536
#define N_SIB 200000
#define N_GP 200000
#define N_GSIB 300000
#define OUT_TOTAL (N_ARC + N_SIB + N_GP + N_GSIB)

// ---------------- device scratch (no allocations allowed) ----------------
__device__ float g_zin[2][SEQ][G4];          // precomputed input gate contributions
__device__ float g_states[SEQ][2 * H];       // BiLSTM outputs [seq, 2H]
__device__ float g_tab[12][TABROWS][M];      // projection tables (+ null row at 256)
__device__ float g_h[2][2][H];               // double-buffered h per direction
__device__ unsigned int g_bar[2];            // per-direction step barriers

// ---------------- fast transcendentals (rel err ~1e-6, safe at +-inf) ----
__device__ __forceinline__ float ftanh(float x) {
    float e = __expf(2.f * x);                 // FMUL + MUFU.EX2
    return 1.f - __fdividef(2.f, e + 1.f);     // FADD + RCP + FMUL + FADD
}
__device__ __forceinline__ float fsig(float x) {
    return __fdividef(1.f, 1.f + __expf(-x));
}

// ---------------- kernel 0: zero output + reset barriers ----------------
__global__ void setup_kernel(float* __restrict__ out, int n) {
    int i = blockIdx.x * blockDim.x + threadIdx.x;
    if (i < n) out[i] = 0.f;
    if (i < 2) g_bar[i] = 0u;
}

// ---------------- kernel 1: embeddings + z_in = xs @ Wih.T + b ----------------
__global__ void __launch_bounds__(256) zin_kernel(
    const int* __restrict__ words, const int* __restrict__ tags,
    const float* __restrict__ word_emb, const float* __restrict__ tag_emb,
    const float* __restrict__ Wih_f, const float* __restrict__ b_f,
    const float* __restrict__ Wih_b, const float* __restrict__ b_b)
{
    __shared__ __align__(16) float xs[2][4][INDIM];
    int tid = threadIdx.x;
    int s_base = blockIdx.x * 4;

    for (int i = tid; i < 2 * 4 * INDIM; i += 256) {
        int dirr = i / (4 * INDIM);
        int jj = (i / INDIM) & 3;
        int k = i % INDIM;
        int s = s_base + jj;
        int pos = dirr ? (SEQ - 1 - s) : s;  // backward LSTM consumes reversed x
        float v = (k < WE) ? word_emb[words[pos] * WE + k]
                           : tag_emb[tags[pos] * TE + (k - WE)];
        xs[dirr][jj][k] = v;
    }
    __syncthreads();

    for (int o = tid; o < 2 * G4; o += 256) {
        int dirr = o / G4;
        int row = o - dirr * G4;
        const float* Wp = dirr ? Wih_b : Wih_f;
        float bias = (dirr ? b_b : b_f)[row];
        const float4* wr = (const float4*)(Wp + row * INDIM);
        float a0 = 0.f, a1 = 0.f, a2 = 0.f, a3 = 0.f;
        #pragma unroll
        for (int k = 0; k < INDIM / 4; k++) {
            float4 w = __ldg(wr + k);
            const float* x0 = &xs[dirr][0][k * 4];
            const float* x1 = &xs[dirr][1][k * 4];
            const float* x2 = &xs[dirr][2][k * 4];
            const float* x3 = &xs[dirr][3][k * 4];
            a0 += w.x * x0[0] + w.y * x0[1] + w.z * x0[2] + w.w * x0[3];
            a1 += w.x * x1[0] + w.y * x1[1] + w.z * x1[2] + w.w * x1[3];
            a2 += w.x * x2[0] + w.y * x2[1] + w.z * x2[2] + w.w * x2[3];
            a3 += w.x * x3[0] + w.y * x3[1] + w.z * x3[2] + w.w * x3[3];
        }
        g_zin[dirr][s_base + 0][row] = a0 + bias;
        g_zin[dirr][s_base + 1][row] = a1 + bias;
        g_zin[dirr][s_base + 2][row] = a2 + bias;
        g_zin[dirr][s_base + 3][row] = a3 + bias;
    }
}

// ---------------- kernel 2: BiLSTM scan, 16 CTAs per direction ----------------
// Weights live in SMEM (160KB, per-thread-contiguous -> conflict-free LDS.128).
// Grid barrier: one red.release + ld.acquire spin per CTA (CG grid.sync pattern).
__global__ void __launch_bounds__(512) lstm_kernel(
    const float* __restrict__ Whh_f, const float* __restrict__ Whh_b)
{
    extern __shared__ float wsm[];               // 400 threads * 100 floats
    __shared__ __align__(16) float h_sm[H];
    __shared__ float z_sm[100];
    __shared__ float c_sm[25];

    int dir = blockIdx.x >> 4;
    int slice = blockIdx.x & 15;
    int j0 = slice * 25;
    const float* Whh = dir ? Whh_b : Whh_f;
    int tid = threadIdx.x;

    // stage weights: logical row lrow = gate*25+jj -> global row gate*400+j0+jj
    // owner thread t = lrow*4 + col/100 holds cols [q*100, q*100+100)
    for (int i = tid; i < 100 * 400; i += 512) {
        int lrow = i / 400, col = i - lrow * 400;
        int gate = lrow / 25, jj = lrow - gate * 25;
        wsm[(lrow * 4 + (col / 100)) * 100 + (col % 100)] =
            Whh[(gate * 400 + j0 + jj) * 400 + col];
    }
    if (tid < H) h_sm[tid] = 0.f;
    if (tid < 25) c_sm[tid] = 0.f;
    __syncthreads();

    int r = tid >> 2, q = tid & 3;
    const float4* wp = (const float4*)(wsm + tid * 100);
    const float4* hp = (const float4*)(h_sm + q * 100);

    unsigned int target = 16;
    for (int step = 0; step < SEQ; step++) {
        // partial dot: thread (r,q) does 100 MACs of row r over cols [q*100,...)
        float acc = 0.f;
        if (tid < 400) {
            #pragma unroll
            for (int k = 0; k < 25; k++) {
                float4 w = wp[k];
                float4 h4 = hp[k];
                acc += w.x * h4.x + w.y * h4.y + w.z * h4.z + w.w * h4.w;
            }
        }
        acc += __shfl_down_sync(0xffffffffu, acc, 2, 4);
        acc += __shfl_down_sync(0xffffffffu, acc, 1, 4);
        if (q == 0 && r < 100) z_sm[r] = acc;
        __syncthreads();

        if (tid < 25) {
            const float* zin = &g_zin[dir][step][0];
            float zi = z_sm[tid]      + __ldg(zin + 0 * H + j0 + tid);
            float zf = z_sm[25 + tid] + __ldg(zin + 1 * H + j0 + tid);
            float zg = z_sm[50 + tid] + __ldg(zin + 2 * H + j0 + tid);
            float zo = z_sm[75 + tid] + __ldg(zin + 3 * H + j0 + tid);
            float ig = fsig(zi), fg = fsig(zf), og = fsig(zo);
            float gg = ftanh(zg);
            float c = fg * c_sm[tid] + ig * gg;
            c_sm[tid] = c;
            float h = og * ftanh(c);
            __stcg(&g_h[(step + 1) & 1][dir][j0 + tid], h);
            int tpos = dir ? (SEQ - 1 - step) : step;
            g_states[tpos][dir * H + j0 + tid] = h;
        }
        __syncthreads();

        // grid barrier (per direction): release-arrive + acquire-spin by tid 0
        if (tid == 0) {
            asm volatile("red.release.gpu.global.add.u32 [%0], 1;"
                         :: "l"(&g_bar[dir]) : "memory");
            unsigned int v;
            do {
                asm volatile("ld.acquire.gpu.global.u32 %0, [%1];"
                             : "=r"(v) : "l"(&g_bar[dir]) : "memory");
            } while (v < target);
        }
        __syncthreads();
        target += 16;

        if (step < SEQ - 1) {
            if (tid < 100)
                *(float4*)(h_sm + tid * 4) =
                    __ldcg((const float4*)&g_h[(step + 1) & 1][dir][tid * 4]);
            __syncthreads();
        }
    }
}

// ---------------- kernel 3: proj[p,s,m] = W_proj[p,m,:] . states[s,:] ----------------
// m-blocked x2: thread t<100 computes m=t and m=t+100 for 8 sequence rows.
__global__ void __launch_bounds__(128) proj_kernel(
    const float* __restrict__ W_proj, const float* __restrict__ null_sib)
{
    int p = blockIdx.x;       // 0..11
    int s0 = blockIdx.y * 8;  // 8 sequence rows per block
    __shared__ __align__(16) float st[8][2 * H];
    int tid = threadIdx.x;
    for (int i = tid; i < 8 * 2 * H; i += 128)
        st[i / (2 * H)][i % (2 * H)] = g_states[s0 + i / (2 * H)][i % (2 * H)];
    __syncthreads();

    if (tid < 100) {
        float acc0[8], acc1[8];
        #pragma unroll
        for (int s = 0; s < 8; s++) { acc0[s] = 0.f; acc1[s] = 0.f; }
        const float4* w0 = (const float4*)(W_proj + ((size_t)p * M + tid) * 2 * H);
        const float4* w1 = (const float4*)(W_proj + ((size_t)p * M + tid + 100) * 2 * H);
        for (int k = 0; k < (2 * H) / 4; k++) {
            float4 a = __ldg(w0 + k);
            float4 b = __ldg(w1 + k);
            #pragma unroll
            for (int s = 0; s < 8; s++) {
                float4 sv = *(const float4*)&st[s][k * 4];
                acc0[s] += a.x * sv.x + a.y * sv.y + a.z * sv.z + a.w * sv.w;
                acc1[s] += b.x * sv.x + b.y * sv.y + b.z * sv.z + b.w * sv.w;
            }
        }
        #pragma unroll
        for (int s = 0; s < 8; s++) {
            g_tab[p][s0 + s][tid] = acc0[s];
            g_tab[p][s0 + s][tid + 100] = acc1[s];
        }
        if ((p == 7 || p == 10) && blockIdx.y == 0) {
            g_tab[p][256][tid] = null_sib[tid];        // null_sib row
            g_tab[p][256][tid + 100] = null_sib[tid + 100];
        }
    }
}

// ---------------- kernel 4: scoring, smem-staged tables, warp-per-tuple ----------------
template <int T>
__global__ void __launch_bounds__(512) score_kernel(
    int p0, int p1, int p2, int p3,
    const int* __restrict__ i0, const int* __restrict__ i1,
    const int* __restrict__ i2, const int* __restrict__ i3,
    const float* __restrict__ ws, float* __restrict__ out, int N)
{
    extern __shared__ float smem[];
    const int m0 = blockIdx.x * MC;

    // stage table m-chunks into shared memory
    int pp[4] = {p0, p1, p2, p3};
    int total = T * TABROWS * MC;
    for (int i = threadIdx.x; i < total; i += blockDim.x) {
        int t = i / (TABROWS * MC);
        int rem = i - t * (TABROWS * MC);
        int s = rem / MC, mm = rem - s * MC;
        smem[i] = g_tab[pp[t]][s][m0 + mm];
    }
    int lane = threadIdx.x & 31;
    float ws0 = ws[m0 + lane];
    float ws1 = (lane < MC - 32) ? ws[m0 + 32 + lane] : 0.f;
    __syncthreads();

    const float* T0 = smem;
    const float* T1 = smem + TABROWS * MC;
    const float* T2 = smem + 2 * TABROWS * MC;
    const float* T3 = smem + 3 * TABROWS * MC;

    int wid = threadIdx.x >> 5;
    int gw = blockIdx.y * (blockDim.x >> 5) + wid;
    int nw = gridDim.y * (blockDim.x >> 5);

    for (int base = gw * 32; base < N; base += nw * 32) {
        int n = min(32, N - base);
        int a0 = 0, a1 = 0, a2 = 0, a3 = 0;
        if (lane < n) {
            a0 = i0[base + lane];
            a1 = i1[base + lane];
            if (T > 2) a2 = i2[base + lane];
            if (T > 3) a3 = i3[base + lane];
        }
        for (int j = 0; j < n; j++) {
            int h  = __shfl_sync(0xffffffffu, a0, j);
            int mo = __shfl_sync(0xffffffffu, a1, j);
            int si = (T > 2) ? __shfl_sync(0xffffffffu, a2, j) : 0;
            int gr = (T > 3) ? __shfl_sync(0xffffffffu, a3, j) : 0;

            float v = T0[h * MC + lane] + T1[mo * MC + lane];
            if (T > 2) v += T2[si * MC + lane];
            if (T > 3) v += T3[gr * MC + lane];
            float acc = ws0 * ftanh(v);
            if (lane < MC - 32) {
                float v1 = T0[h * MC + 32 + lane] + T1[mo * MC + 32 + lane];
                if (T > 2) v1 += T2[si * MC + 32 + lane];
                if (T > 3) v1 += T3[gr * MC + 32 + lane];
                acc += ws1 * ftanh(v1);
            }
            #pragma unroll
            for (int off = 16; off; off >>= 1)
                acc += __shfl_xor_sync(0xffffffffu, acc, off);
            if (lane == 0) atomicAdd(&out[base + j], acc);
        }
    }
}

// ---------------- host launcher ----------------
extern "C" void kernel_launch(void* const* d_in, const int* in_sizes, int n_in,
                              void* d_out, int out_size)
{
    const int* words      = (const int*)d_in[0];
    const int* tags       = (const int*)d_in[1];
    const int* arc_head   = (const int*)d_in[2];
    const int* arc_mod    = (const int*)d_in[3];
    const int* sib_head   = (const int*)d_in[4];
    const int* sib_mod    = (const int*)d_in[5];
    const int* sib_sib    = (const int*)d_in[6];
    const int* gp_head    = (const int*)d_in[7];
    const int* gp_mod     = (const int*)d_in[8];
    const int* gp_grand   = (const int*)d_in[9];
    const int* gsib_head  = (const int*)d_in[10];
    const int* gsib_mod   = (const int*)d_in[11];
    const int* gsib_sib   = (const int*)d_in[12];
    const int* gsib_grand = (const int*)d_in[13];
    const float* word_emb = (const float*)d_in[14];
    const float* tag_emb  = (const float*)d_in[15];
    const float* Wih_f    = (const float*)d_in[16];
    const float* Whh_f    = (const float*)d_in[17];
    const float* b_f      = (const float*)d_in[18];
    const float* Wih_b    = (const float*)d_in[19];
    const float* Whh_b    = (const float*)d_in[20];
    const float* b_b      = (const float*)d_in[21];
    const float* W_proj   = (const float*)d_in[22];
    const float* W_score  = (const float*)d_in[23];
    const float* null_sib = (const float*)d_in[24];
    float* out = (float*)d_out;

    // opt-in dynamic smem (idempotent, non-stream API)
    cudaFuncSetAttribute(lstm_kernel, cudaFuncAttributeMaxDynamicSharedMemorySize,
                         100 * 400 * (int)sizeof(float));
    cudaFuncSetAttribute(score_kernel<2>, cudaFuncAttributeMaxDynamicSharedMemorySize,
                         2 * TABROWS * MC * (int)sizeof(float));
    cudaFuncSetAttribute(score_kernel<3>, cudaFuncAttributeMaxDynamicSharedMemorySize,
                         3 * TABROWS * MC * (int)sizeof(float));
    cudaFuncSetAttribute(score_kernel<4>, cudaFuncAttributeMaxDynamicSharedMemorySize,
                         4 * TABROWS * MC * (int)sizeof(float));

    setup_kernel<<<(OUT_TOTAL + 511) / 512, 512>>>(out, OUT_TOTAL);
    zin_kernel<<<SEQ / 4, 256>>>(words, tags, word_emb, tag_emb,
                                 Wih_f, b_f, Wih_b, b_b);
    lstm_kernel<<<32, 512, 100 * 400 * sizeof(float)>>>(Whh_f, Whh_b);
    proj_kernel<<<dim3(12, 32), 128>>>(W_proj, null_sib);

    dim3 sgrid(NCHUNK, 37);
    score_kernel<2><<<sgrid, 512, 2 * TABROWS * MC * sizeof(float)>>>(
        0, 1, 0, 0, arc_head, arc_mod, nullptr, nullptr,
        W_score + 0 * M, out, N_ARC);
    score_kernel<3><<<sgrid, 512, 3 * TABROWS * MC * sizeof(float)>>>(
        5, 6, 7, 0, sib_head, sib_mod, sib_sib, nullptr,
        W_score + 1 * M, out + N_ARC, N_SIB);
    score_kernel<3><<<sgrid, 512, 3 * TABROWS * MC * sizeof(float)>>>(
        3, 4, 2, 0, gp_head, gp_mod, gp_grand, nullptr,
        W_score + 2 * M, out + N_ARC + N_SIB, N_GP);
    score_kernel<4><<<sgrid, 512, 4 * TABROWS * MC * sizeof(float)>>>(
        8, 9, 10, 11, gsib_head, gsib_mod, gsib_sib, gsib_grand,
        W_score + 3 * M, out + N_ARC + N_SIB + N_GP, N_GSIB);
}

// round 5
// speedup vs baseline: 1.9384x; 1.0854x over previous
#include <cuda_runtime.h>
#include <math.h>

#define SEQ 256
#define WE 100
#define TE 20
#define INDIM 120
#define H 400
#define G4 1600
#define M 200
#define TABROWS 257
#define N_ARC 65536
#define N_SIB 200000
#define N_GP 200000
#define N_GSIB 300000
#define OUT_TOTAL (N_ARC + N_SIB + N_GP + N_GSIB)

// ---------------- device scratch (no allocations allowed) ----------------
__device__ float g_zin[2][SEQ][G4];          // precomputed input gate contributions
__device__ float g_states[SEQ][2 * H];       // BiLSTM outputs [seq, 2H]
__device__ float g_tab[12][TABROWS][M];      // projection tables (+ null row at 256)
__device__ float g_h[2][2][H];               // double-buffered h per direction
__device__ unsigned int g_bar[2];            // per-direction step barriers

// ---------------- fast transcendentals (rel err ~1e-6, safe at +-inf) ----
__device__ __forceinline__ float ftanh(float x) {
    float e = __expf(2.f * x);
    return 1.f - __fdividef(2.f, e + 1.f);
}
__device__ __forceinline__ float fsig(float x) {
    return __fdividef(1.f, 1.f + __expf(-x));
}

// ---------------- kernel 0: zero output + reset barriers ----------------
__global__ void setup_kernel(float* __restrict__ out, int n) {
    int i = blockIdx.x * blockDim.x + threadIdx.x;
    if (i < n) out[i] = 0.f;
    if (i < 2) g_bar[i] = 0u;
}

// ---------------- kernel 1: embeddings + z_in = xs @ Wih.T + b ----------------
__global__ void __launch_bounds__(256) zin_kernel(
    const int* __restrict__ words, const int* __restrict__ tags,
    const float* __restrict__ word_emb, const float* __restrict__ tag_emb,
    const float* __restrict__ Wih_f, const float* __restrict__ b_f,
    const float* __restrict__ Wih_b, const float* __restrict__ b_b)
{
    __shared__ __align__(16) float xs[2][4][INDIM];
    int tid = threadIdx.x;
    int s_base = blockIdx.x * 4;

    for (int i = tid; i < 2 * 4 * INDIM; i += 256) {
        int dirr = i / (4 * INDIM);
        int jj = (i / INDIM) & 3;
        int k = i % INDIM;
        int s = s_base + jj;
        int pos = dirr ? (SEQ - 1 - s) : s;  // backward LSTM consumes reversed x
        float v = (k < WE) ? word_emb[words[pos] * WE + k]
                           : tag_emb[tags[pos] * TE + (k - WE)];
        xs[dirr][jj][k] = v;
    }
    __syncthreads();

    for (int o = tid; o < 2 * G4; o += 256) {
        int dirr = o / G4;
        int row = o - dirr * G4;
        const float* Wp = dirr ? Wih_b : Wih_f;
        float bias = (dirr ? b_b : b_f)[row];
        const float4* wr = (const float4*)(Wp + row * INDIM);
        float a0 = 0.f, a1 = 0.f, a2 = 0.f, a3 = 0.f;
        #pragma unroll
        for (int k = 0; k < INDIM / 4; k++) {
            float4 w = __ldg(wr + k);
            const float* x0 = &xs[dirr][0][k * 4];
            const float* x1 = &xs[dirr][1][k * 4];
            const float* x2 = &xs[dirr][2][k * 4];
            const float* x3 = &xs[dirr][3][k * 4];
            a0 += w.x * x0[0] + w.y * x0[1] + w.z * x0[2] + w.w * x0[3];
            a1 += w.x * x1[0] + w.y * x1[1] + w.z * x1[2] + w.w * x1[3];
            a2 += w.x * x2[0] + w.y * x2[1] + w.z * x2[2] + w.w * x2[3];
            a3 += w.x * x3[0] + w.y * x3[1] + w.z * x3[2] + w.w * x3[3];
        }
        g_zin[dirr][s_base + 0][row] = a0 + bias;
        g_zin[dirr][s_base + 1][row] = a1 + bias;
        g_zin[dirr][s_base + 2][row] = a2 + bias;
        g_zin[dirr][s_base + 3][row] = a3 + bias;
    }
}

// ---------------- kernel 2: BiLSTM scan, 16 CTAs per direction ----------------
// Weights live in REGISTERS: thread (r,q) holds 100 floats of row r, cols [q*100,..).
// Per step: 25 broadcast LDS of h + 100 FFMA, shfl-reduce by 4, gates,
// grid barrier (red.release + ld.acquire spin), h exchange via L2 (.cg).
__global__ void __launch_bounds__(512, 1) lstm_kernel(
    const float* __restrict__ Whh_f, const float* __restrict__ Whh_b)
{
    __shared__ __align__(16) float h_sm[H];
    __shared__ float z_sm[100];
    __shared__ float c_sm[25];

    int dir = blockIdx.x >> 4;
    int slice = blockIdx.x & 15;
    int j0 = slice * 25;
    const float* Whh = dir ? Whh_b : Whh_f;
    int tid = threadIdx.x;
    int r = tid >> 2, q = tid & 3;

    // load this thread's weight strip into registers (rows clamped for padding threads)
    float4 w[25];
    {
        int rr = (r < 100) ? r : 99;
        int gate = rr / 25, jj = rr - gate * 25;
        const float4* wrow = (const float4*)(Whh + (gate * 400 + j0 + jj) * H + q * 100);
        #pragma unroll
        for (int k = 0; k < 25; k++) w[k] = __ldg(wrow + k);
    }

    if (tid < H) h_sm[tid] = 0.f;
    if (tid < 25) c_sm[tid] = 0.f;
    __syncthreads();

    const float4* hp = (const float4*)(h_sm + q * 100);
    unsigned int target = 16;

    for (int step = 0; step < SEQ; step++) {
        // partial dot with 4 rotating accumulators
        float a0 = 0.f, a1 = 0.f, a2 = 0.f, a3 = 0.f;
        #pragma unroll
        for (int k = 0; k < 24; k += 4) {
            float4 h0 = hp[k],     h1 = hp[k + 1];
            float4 h2 = hp[k + 2], h3 = hp[k + 3];
            a0 += w[k].x * h0.x + w[k].y * h0.y + w[k].z * h0.z + w[k].w * h0.w;
            a1 += w[k+1].x * h1.x + w[k+1].y * h1.y + w[k+1].z * h1.z + w[k+1].w * h1.w;
            a2 += w[k+2].x * h2.x + w[k+2].y * h2.y + w[k+2].z * h2.z + w[k+2].w * h2.w;
            a3 += w[k+3].x * h3.x + w[k+3].y * h3.y + w[k+3].z * h3.z + w[k+3].w * h3.w;
        }
        {
            float4 h24 = hp[24];
            a0 += w[24].x * h24.x + w[24].y * h24.y + w[24].z * h24.z + w[24].w * h24.w;
        }
        float acc = (a0 + a1) + (a2 + a3);
        acc += __shfl_down_sync(0xffffffffu, acc, 2, 4);
        acc += __shfl_down_sync(0xffffffffu, acc, 1, 4);
        if (q == 0 && r < 100) z_sm[r] = acc;
        __syncthreads();

        if (tid < 25) {
            const float* zin = &g_zin[dir][step][0];
            float zi = z_sm[tid]      + __ldg(zin + 0 * H + j0 + tid);
            float zf = z_sm[25 + tid] + __ldg(zin + 1 * H + j0 + tid);
            float zg = z_sm[50 + tid] + __ldg(zin + 2 * H + j0 + tid);
            float zo = z_sm[75 + tid] + __ldg(zin + 3 * H + j0 + tid);
            float ig = fsig(zi), fg = fsig(zf), og = fsig(zo);
            float gg = ftanh(zg);
            float c = fg * c_sm[tid] + ig * gg;
            c_sm[tid] = c;
            float h = og * ftanh(c);
            __stcg(&g_h[(step + 1) & 1][dir][j0 + tid], h);
            int tpos = dir ? (SEQ - 1 - step) : step;
            g_states[tpos][dir * H + j0 + tid] = h;
        }
        __syncthreads();

        // grid barrier (per direction)
        if (tid == 0) {
            asm volatile("red.release.gpu.global.add.u32 [%0], 1;"
                         :: "l"(&g_bar[dir]) : "memory");
            unsigned int v;
            do {
                asm volatile("ld.acquire.gpu.global.u32 %0, [%1];"
                             : "=r"(v) : "l"(&g_bar[dir]) : "memory");
            } while (v < target);
        }
        __syncthreads();
        target += 16;

        if (step < SEQ - 1) {
            if (tid < 100)
                *(float4*)(h_sm + tid * 4) =
                    __ldcg((const float4*)&g_h[(step + 1) & 1][dir][tid * 4]);
            __syncthreads();
        }
    }
}

// ---------------- kernel 3: proj[p,s,m] = W_proj[p,m,:] . states[s,:] ----------------
// 256 threads, 200 active (1 m each), 8 seq rows, k unrolled x2 for MLP.
__global__ void __launch_bounds__(256) proj_kernel(
    const float* __restrict__ W_proj, const float* __restrict__ null_sib)
{
    int p = blockIdx.x;       // 0..11
    int s0 = blockIdx.y * 8;  // 8 sequence rows per block
    __shared__ __align__(16) float st[8][2 * H];
    int tid = threadIdx.x;
    for (int i = tid; i < 8 * 2 * H; i += 256)
        st[i / (2 * H)][i % (2 * H)] = g_states[s0 + i / (2 * H)][i % (2 * H)];
    __syncthreads();

    if (tid < M) {
        float acc[8];
        #pragma unroll
        for (int s = 0; s < 8; s++) acc[s] = 0.f;
        const float4* w = (const float4*)(W_proj + ((size_t)p * M + tid) * 2 * H);
        #pragma unroll 2
        for (int k = 0; k < (2 * H) / 4; k++) {
            float4 wv = __ldg(w + k);
            #pragma unroll
            for (int s = 0; s < 8; s++) {
                float4 sv = *(const float4*)&st[s][k * 4];
                acc[s] += wv.x * sv.x + wv.y * sv.y + wv.z * sv.z + wv.w * sv.w;
            }
        }
        #pragma unroll
        for (int s = 0; s < 8; s++)
            g_tab[p][s0 + s][tid] = acc[s];
        if ((p == 7 || p == 10) && blockIdx.y == 0)
            g_tab[p][256][tid] = null_sib[tid];   // null_sib row
    }
}

// ---------------- kernel 4: scoring, smem tables, warp-per-tuple, 2-tuple ILP ----
template <int T>
__global__ void __launch_bounds__(512) score_kernel(
    int p0, int p1, int p2, int p3,
    const int* __restrict__ i0, const int* __restrict__ i1,
    const int* __restrict__ i2, const int* __restrict__ i3,
    const float* __restrict__ ws, float* __restrict__ out, int N, int mc_nom)
{
    extern __shared__ float smem[];
    const int m0 = blockIdx.x * mc_nom;
    const int mc = min(mc_nom, M - m0);

    // stage table m-chunks + ws into shared memory
    int pp[4] = {p0, p1, p2, p3};
    #pragma unroll
    for (int t = 0; t < T; t++) {
        const float* src = &g_tab[pp[t]][0][0];
        float* dst = smem + t * TABROWS * mc;
        for (int i = threadIdx.x; i < TABROWS * mc; i += blockDim.x) {
            int s = i / mc, mm = i - s * mc;
            dst[i] = src[s * M + m0 + mm];
        }
    }
    float* ws_sm = smem + T * TABROWS * mc;
    if (threadIdx.x < mc) ws_sm[threadIdx.x] = ws[m0 + threadIdx.x];
    __syncthreads();

    const float* T0 = smem;
    const float* T1 = smem + TABROWS * mc;
    const float* T2 = smem + 2 * TABROWS * mc;
    const float* T3 = smem + 3 * TABROWS * mc;

    int lane = threadIdx.x & 31;
    int wid = threadIdx.x >> 5;
    int gw = blockIdx.y * (blockDim.x >> 5) + wid;
    int nw = gridDim.y * (blockDim.x >> 5);

    for (int base = gw * 32; base < N; base += nw * 32) {
        int n = min(32, N - base);
        int a0 = 0, a1 = 0, a2 = 0, a3 = 0;
        if (lane < n) {
            a0 = i0[base + lane];
            a1 = i1[base + lane];
            if (T > 2) a2 = i2[base + lane];
            if (T > 3) a3 = i3[base + lane];
        }
        for (int j = 0; j < n; j += 2) {
            int hA  = __shfl_sync(0xffffffffu, a0, j);
            int moA = __shfl_sync(0xffffffffu, a1, j);
            int siA = (T > 2) ? __shfl_sync(0xffffffffu, a2, j) : 0;
            int grA = (T > 3) ? __shfl_sync(0xffffffffu, a3, j) : 0;
            int j2 = (j + 1 < n) ? (j + 1) : j;      // dup (discarded) at tail
            int hB  = __shfl_sync(0xffffffffu, a0, j2);
            int moB = __shfl_sync(0xffffffffu, a1, j2);
            int siB = (T > 2) ? __shfl_sync(0xffffffffu, a2, j2) : 0;
            int grB = (T > 3) ? __shfl_sync(0xffffffffu, a3, j2) : 0;

            float accA = 0.f, accB = 0.f;
            for (int mm = lane; mm < mc; mm += 32) {
                float vA = T0[hA * mc + mm] + T1[moA * mc + mm];
                float vB = T0[hB * mc + mm] + T1[moB * mc + mm];
                if (T > 2) { vA += T2[siA * mc + mm]; vB += T2[siB * mc + mm]; }
                if (T > 3) { vA += T3[grA * mc + mm]; vB += T3[grB * mc + mm]; }
                float wsv = ws_sm[mm];
                accA += wsv * ftanh(vA);
                accB += wsv * ftanh(vB);
            }
            #pragma unroll
            for (int off = 16; off; off >>= 1) {
                accA += __shfl_xor_sync(0xffffffffu, accA, off);
                accB += __shfl_xor_sync(0xffffffffu, accB, off);
            }
            if (lane == 0) {
                atomicAdd(&out[base + j], accA);
                if (j + 1 < n) atomicAdd(&out[base + j + 1], accB);
            }
        }
    }
}

// ---------------- host launcher ----------------
extern "C" void kernel_launch(void* const* d_in, const int* in_sizes, int n_in,
                              void* d_out, int out_size)
{
    const int* words      = (const int*)d_in[0];
    const int* tags       = (const int*)d_in[1];
    const int* arc_head   = (const int*)d_in[2];
    const int* arc_mod    = (const int*)d_in[3];
    const int* sib_head   = (const int*)d_in[4];
    const int* sib_mod    = (const int*)d_in[5];
    const int* sib_sib    = (const int*)d_in[6];
    const int* gp_head    = (const int*)d_in[7];
    const int* gp_mod     = (const int*)d_in[8];
    const int* gp_grand   = (const int*)d_in[9];
    const int* gsib_head  = (const int*)d_in[10];
    const int* gsib_mod   = (const int*)d_in[11];
    const int* gsib_sib   = (const int*)d_in[12];
    const int* gsib_grand = (const int*)d_in[13];
    const float* word_emb = (const float*)d_in[14];
    const float* tag_emb  = (const float*)d_in[15];
    const float* Wih_f    = (const float*)d_in[16];
    const float* Whh_f    = (const float*)d_in[17];
    const float* b_f      = (const float*)d_in[18];
    const float* Wih_b    = (const float*)d_in[19];
    const float* Whh_b    = (const float*)d_in[20];
    const float* b_b      = (const float*)d_in[21];
    const float* W_proj   = (const float*)d_in[22];
    const float* W_score  = (const float*)d_in[23];
    const float* null_sib = (const float*)d_in[24];
    float* out = (float*)d_out;

    // smem sizes: T tables of 257*mc floats + mc floats of ws
    const int smem2 = (2 * TABROWS * 100 + 100) * (int)sizeof(float); // 205.6 KB
    const int smem3 = (3 * TABROWS * 68 + 68) * (int)sizeof(float);   // 210.0 KB
    const int smem4 = (4 * TABROWS * 50 + 50) * (int)sizeof(float);   // 205.8 KB

    cudaFuncSetAttribute(score_kernel<2>, cudaFuncAttributeMaxDynamicSharedMemorySize, smem2);
    cudaFuncSetAttribute(score_kernel<3>, cudaFuncAttributeMaxDynamicSharedMemorySize, smem3);
    cudaFuncSetAttribute(score_kernel<4>, cudaFuncAttributeMaxDynamicSharedMemorySize, smem4);

    setup_kernel<<<(OUT_TOTAL + 511) / 512, 512>>>(out, OUT_TOTAL);
    zin_kernel<<<SEQ / 4, 256>>>(words, tags, word_emb, tag_emb,
                                 Wih_f, b_f, Wih_b, b_b);
    lstm_kernel<<<32, 512>>>(Whh_f, Whh_b);
    proj_kernel<<<dim3(12, 32), 256>>>(W_proj, null_sib);

    score_kernel<2><<<dim3(2, 74), 512, smem2>>>(
        0, 1, 0, 0, arc_head, arc_mod, nullptr, nullptr,
        W_score + 0 * M, out, N_ARC, 100);
    score_kernel<3><<<dim3(3, 49), 512, smem3>>>(
        5, 6, 7, 0, sib_head, sib_mod, sib_sib, nullptr,
        W_score + 1 * M, out + N_ARC, N_SIB, 68);
    score_kernel<3><<<dim3(3, 49), 512, smem3>>>(
        3, 4, 2, 0, gp_head, gp_mod, gp_grand, nullptr,
        W_score + 2 * M, out + N_ARC + N_SIB, N_GP, 68);
    score_kernel<4><<<dim3(4, 37), 512, smem4>>>(
        8, 9, 10, 11, gsib_head, gsib_mod, gsib_sib, gsib_grand,
        W_score + 3 * M, out + N_ARC + N_SIB + N_GP, N_GSIB, 50);
}

// round 6
// speedup vs baseline: 2.3827x; 1.2292x over previous
#include <cuda_runtime.h>
#include <math.h>

#define SEQ 256
#define WE 100
#define TE 20
#define INDIM 120
#define H 400
#define G4 1600
#define M 200
#define TABROWS 257
#define N_ARC 65536
#define N_SIB 200000
#define N_GP 200000
#define N_GSIB 300000
#define OUT_TOTAL (N_ARC + N_SIB + N_GP + N_GSIB)

// LSTM decomposition: 20 CTAs per direction, 20 h-units each
#define LCTA 20
#define JH 20
#define LROWS 80          // 4 gates * 20
#define LTHREADS 320      // 4 threads per row

// ---------------- device scratch (no allocations allowed) ----------------
__device__ float g_zin[2][SEQ][G4];
__device__ float g_states[SEQ][2 * H];
__device__ float g_tab[12][TABROWS][M];
__device__ float g_h[2][2][H];
__device__ unsigned int g_bar[2];

// ---------------- fast transcendentals (rel err ~1e-6, safe at +-inf) ----
__device__ __forceinline__ float ftanh(float x) {
    float e = __expf(2.f * x);
    return 1.f - __fdividef(2.f, e + 1.f);
}
__device__ __forceinline__ float fsig(float x) {
    return __fdividef(1.f, 1.f + __expf(-x));
}

// ---------------- kernel 0: zero output + reset barriers ----------------
__global__ void setup_kernel(float* __restrict__ out, int n) {
    int i = blockIdx.x * blockDim.x + threadIdx.x;
    if (i < n) out[i] = 0.f;
    if (i < 2) g_bar[i] = 0u;
}

// ---------------- kernel 1: embeddings + z_in = xs @ Wih.T + b ----------------
__global__ void __launch_bounds__(256) zin_kernel(
    const int* __restrict__ words, const int* __restrict__ tags,
    const float* __restrict__ word_emb, const float* __restrict__ tag_emb,
    const float* __restrict__ Wih_f, const float* __restrict__ b_f,
    const float* __restrict__ Wih_b, const float* __restrict__ b_b)
{
    __shared__ __align__(16) float xs[2][4][INDIM];
    int tid = threadIdx.x;
    int s_base = blockIdx.x * 4;

    for (int i = tid; i < 2 * 4 * INDIM; i += 256) {
        int dirr = i / (4 * INDIM);
        int jj = (i / INDIM) & 3;
        int k = i % INDIM;
        int s = s_base + jj;
        int pos = dirr ? (SEQ - 1 - s) : s;
        float v = (k < WE) ? word_emb[words[pos] * WE + k]
                           : tag_emb[tags[pos] * TE + (k - WE)];
        xs[dirr][jj][k] = v;
    }
    __syncthreads();

    for (int o = tid; o < 2 * G4; o += 256) {
        int dirr = o / G4;
        int row = o - dirr * G4;
        const float* Wp = dirr ? Wih_b : Wih_f;
        float bias = (dirr ? b_b : b_f)[row];
        const float4* wr = (const float4*)(Wp + row * INDIM);
        float a0 = 0.f, a1 = 0.f, a2 = 0.f, a3 = 0.f;
        #pragma unroll
        for (int k = 0; k < INDIM / 4; k++) {
            float4 w = __ldg(wr + k);
            const float* x0 = &xs[dirr][0][k * 4];
            const float* x1 = &xs[dirr][1][k * 4];
            const float* x2 = &xs[dirr][2][k * 4];
            const float* x3 = &xs[dirr][3][k * 4];
            a0 += w.x * x0[0] + w.y * x0[1] + w.z * x0[2] + w.w * x0[3];
            a1 += w.x * x1[0] + w.y * x1[1] + w.z * x1[2] + w.w * x1[3];
            a2 += w.x * x2[0] + w.y * x2[1] + w.z * x2[2] + w.w * x2[3];
            a3 += w.x * x3[0] + w.y * x3[1] + w.z * x3[2] + w.w * x3[3];
        }
        g_zin[dirr][s_base + 0][row] = a0 + bias;
        g_zin[dirr][s_base + 1][row] = a1 + bias;
        g_zin[dirr][s_base + 2][row] = a2 + bias;
        g_zin[dirr][s_base + 3][row] = a3 + bias;
    }
}

// ---------------- kernel 2: BiLSTM scan, 20 CTAs per direction ----------------
// Thread (r,q): r in [0,80) gate-row, q in [0,4) col-quarter; holds 100 weight
// floats in REGISTERS (320 thr -> 204-reg budget, no spill).
__global__ void __launch_bounds__(LTHREADS, 1) lstm_kernel(
    const float* __restrict__ Whh_f, const float* __restrict__ Whh_b)
{
    __shared__ __align__(16) float h_sm[H];
    __shared__ float z_sm[LROWS];
    __shared__ float c_sm[JH];

    int dir = blockIdx.x / LCTA;
    int slice = blockIdx.x - dir * LCTA;
    int j0 = slice * JH;
    const float* Whh = dir ? Whh_b : Whh_f;
    int tid = threadIdx.x;
    int r = tid >> 2, q = tid & 3;

    // weight strip -> registers
    float4 w[25];
    {
        int gate = r / JH, jj = r - gate * JH;
        const float4* wrow = (const float4*)(Whh + (gate * H + j0 + jj) * H + q * 100);
        #pragma unroll
        for (int k = 0; k < 25; k++) w[k] = __ldg(wrow + k);
    }

    for (int i = tid; i < H; i += LTHREADS) h_sm[i] = 0.f;
    if (tid < JH) c_sm[tid] = 0.f;
    __syncthreads();

    const float4* hp = (const float4*)(h_sm + q * 100);
    unsigned int target = LCTA;

    for (int step = 0; step < SEQ; step++) {
        // prefetch this step's gate inputs (consumed after the dot)
        float pz_i = 0.f, pz_f = 0.f, pz_g = 0.f, pz_o = 0.f;
        if (tid < JH) {
            const float* zin = &g_zin[dir][step][0];
            pz_i = __ldg(zin + 0 * H + j0 + tid);
            pz_f = __ldg(zin + 1 * H + j0 + tid);
            pz_g = __ldg(zin + 2 * H + j0 + tid);
            pz_o = __ldg(zin + 3 * H + j0 + tid);
        }

        // partial dot with 4 rotating accumulators
        float a0 = 0.f, a1 = 0.f, a2 = 0.f, a3 = 0.f;
        #pragma unroll
        for (int k = 0; k < 24; k += 4) {
            float4 h0 = hp[k],     h1 = hp[k + 1];
            float4 h2 = hp[k + 2], h3 = hp[k + 3];
            a0 += w[k].x * h0.x + w[k].y * h0.y + w[k].z * h0.z + w[k].w * h0.w;
            a1 += w[k+1].x * h1.x + w[k+1].y * h1.y + w[k+1].z * h1.z + w[k+1].w * h1.w;
            a2 += w[k+2].x * h2.x + w[k+2].y * h2.y + w[k+2].z * h2.z + w[k+2].w * h2.w;
            a3 += w[k+3].x * h3.x + w[k+3].y * h3.y + w[k+3].z * h3.z + w[k+3].w * h3.w;
        }
        {
            float4 h24 = hp[24];
            a0 += w[24].x * h24.x + w[24].y * h24.y + w[24].z * h24.z + w[24].w * h24.w;
        }
        float acc = (a0 + a1) + (a2 + a3);
        acc += __shfl_down_sync(0xffffffffu, acc, 2, 4);
        acc += __shfl_down_sync(0xffffffffu, acc, 1, 4);
        if (q == 0) z_sm[r] = acc;
        __syncthreads();

        if (tid < JH) {
            float zi = z_sm[tid]           + pz_i;
            float zf = z_sm[JH + tid]      + pz_f;
            float zg = z_sm[2 * JH + tid]  + pz_g;
            float zo = z_sm[3 * JH + tid]  + pz_o;
            float ig = fsig(zi), fg = fsig(zf), og = fsig(zo);
            float gg = ftanh(zg);
            float c = fg * c_sm[tid] + ig * gg;
            c_sm[tid] = c;
            float h = og * ftanh(c);
            __stcg(&g_h[(step + 1) & 1][dir][j0 + tid], h);
            int tpos = dir ? (SEQ - 1 - step) : step;
            g_states[tpos][dir * H + j0 + tid] = h;
        }
        __syncthreads();

        // grid barrier (per direction)
        if (tid == 0) {
            asm volatile("red.release.gpu.global.add.u32 [%0], 1;"
                         :: "l"(&g_bar[dir]) : "memory");
            unsigned int v;
            do {
                asm volatile("ld.acquire.gpu.global.u32 %0, [%1];"
                             : "=r"(v) : "l"(&g_bar[dir]) : "memory");
            } while (v < target);
        }
        __syncthreads();
        target += LCTA;

        if (step < SEQ - 1) {
            if (tid < 100)
                *(float4*)(h_sm + tid * 4) =
                    __ldcg((const float4*)&g_h[(step + 1) & 1][dir][tid * 4]);
            __syncthreads();
        }
    }
}

// ---------------- kernel 3: proj[p,s,m] = W_proj[p,m,:] . states[s,:] ----------------
// 16 seq rows per block (grid 12x16 = 192), 16 register accumulators.
__global__ void __launch_bounds__(256) proj_kernel(
    const float* __restrict__ W_proj, const float* __restrict__ null_sib)
{
    extern __shared__ float st[];              // [16][800]
    int p = blockIdx.x;
    int s0 = blockIdx.y * 16;
    int tid = threadIdx.x;
    for (int i = tid; i < 16 * 2 * H; i += 256)
        st[i] = g_states[s0 + i / (2 * H)][i % (2 * H)];
    __syncthreads();

    if (tid < M) {
        float acc[16];
        #pragma unroll
        for (int s = 0; s < 16; s++) acc[s] = 0.f;
        const float4* w = (const float4*)(W_proj + ((size_t)p * M + tid) * 2 * H);
        #pragma unroll 2
        for (int k = 0; k < (2 * H) / 4; k++) {
            float4 wv = __ldg(w + k);
            #pragma unroll
            for (int s = 0; s < 16; s++) {
                float4 sv = *(const float4*)&st[s * 2 * H + k * 4];
                acc[s] += wv.x * sv.x + wv.y * sv.y + wv.z * sv.z + wv.w * sv.w;
            }
        }
        #pragma unroll
        for (int s = 0; s < 16; s++)
            g_tab[p][s0 + s][tid] = acc[s];
        if ((p == 7 || p == 10) && blockIdx.y == 0)
            g_tab[p][256][tid] = null_sib[tid];
    }
}

// ---------------- kernel 4: scoring, smem tables, warp-per-tuple, 4-tuple ILP ----
template <int T>
__global__ void __launch_bounds__(512) score_kernel(
    int p0, int p1, int p2, int p3,
    const int* __restrict__ i0, const int* __restrict__ i1,
    const int* __restrict__ i2, const int* __restrict__ i3,
    const float* __restrict__ ws, float* __restrict__ out, int N, int mc_nom)
{
    extern __shared__ float smem[];
    const int m0 = blockIdx.x * mc_nom;
    const int mc = min(mc_nom, M - m0);

    int pp[4] = {p0, p1, p2, p3};
    #pragma unroll
    for (int t = 0; t < T; t++) {
        const float* src = &g_tab[pp[t]][0][0];
        float* dst = smem + t * TABROWS * mc;
        for (int i = threadIdx.x; i < TABROWS * mc; i += blockDim.x) {
            int s = i / mc, mm = i - s * mc;
            dst[i] = src[s * M + m0 + mm];
        }
    }
    float* ws_sm = smem + T * TABROWS * mc;
    if (threadIdx.x < mc) ws_sm[threadIdx.x] = ws[m0 + threadIdx.x];
    __syncthreads();

    const float* T0 = smem;
    const float* T1 = smem + TABROWS * mc;
    const float* T2 = smem + 2 * TABROWS * mc;
    const float* T3 = smem + 3 * TABROWS * mc;

    int lane = threadIdx.x & 31;
    int wid = threadIdx.x >> 5;
    int gw = blockIdx.y * (blockDim.x >> 5) + wid;
    int nw = gridDim.y * (blockDim.x >> 5);

    for (int base = gw * 32; base < N; base += nw * 32) {
        int n = min(32, N - base);
        int a0 = 0, a1 = 0, a2 = 0, a3 = 0;
        if (lane < n) {
            a0 = i0[base + lane];
            a1 = i1[base + lane];
            if (T > 2) a2 = i2[base + lane];
            if (T > 3) a3 = i3[base + lane];
        }
        for (int j = 0; j < n; j += 4) {
            int jB = min(j + 1, n - 1), jC = min(j + 2, n - 1), jD = min(j + 3, n - 1);
            int hA  = __shfl_sync(0xffffffffu, a0, j);
            int hB  = __shfl_sync(0xffffffffu, a0, jB);
            int hC  = __shfl_sync(0xffffffffu, a0, jC);
            int hD  = __shfl_sync(0xffffffffu, a0, jD);
            int moA = __shfl_sync(0xffffffffu, a1, j);
            int moB = __shfl_sync(0xffffffffu, a1, jB);
            int moC = __shfl_sync(0xffffffffu, a1, jC);
            int moD = __shfl_sync(0xffffffffu, a1, jD);
            int siA = 0, siB = 0, siC = 0, siD = 0, grA = 0, grB = 0, grC = 0, grD = 0;
            if (T > 2) {
                siA = __shfl_sync(0xffffffffu, a2, j);
                siB = __shfl_sync(0xffffffffu, a2, jB);
                siC = __shfl_sync(0xffffffffu, a2, jC);
                siD = __shfl_sync(0xffffffffu, a2, jD);
            }
            if (T > 3) {
                grA = __shfl_sync(0xffffffffu, a3, j);
                grB = __shfl_sync(0xffffffffu, a3, jB);
                grC = __shfl_sync(0xffffffffu, a3, jC);
                grD = __shfl_sync(0xffffffffu, a3, jD);
            }

            float accA = 0.f, accB = 0.f, accC = 0.f, accD = 0.f;
            for (int mm = lane; mm < mc; mm += 32) {
                float wsv = ws_sm[mm];
                float vA = T0[hA * mc + mm] + T1[moA * mc + mm];
                float vB = T0[hB * mc + mm] + T1[moB * mc + mm];
                float vC = T0[hC * mc + mm] + T1[moC * mc + mm];
                float vD = T0[hD * mc + mm] + T1[moD * mc + mm];
                if (T > 2) {
                    vA += T2[siA * mc + mm]; vB += T2[siB * mc + mm];
                    vC += T2[siC * mc + mm]; vD += T2[siD * mc + mm];
                }
                if (T > 3) {
                    vA += T3[grA * mc + mm]; vB += T3[grB * mc + mm];
                    vC += T3[grC * mc + mm]; vD += T3[grD * mc + mm];
                }
                accA += wsv * ftanh(vA);
                accB += wsv * ftanh(vB);
                accC += wsv * ftanh(vC);
                accD += wsv * ftanh(vD);
            }
            #pragma unroll
            for (int off = 16; off; off >>= 1) {
                accA += __shfl_xor_sync(0xffffffffu, accA, off);
                accB += __shfl_xor_sync(0xffffffffu, accB, off);
                accC += __shfl_xor_sync(0xffffffffu, accC, off);
                accD += __shfl_xor_sync(0xffffffffu, accD, off);
            }
            if (lane == 0) {
                atomicAdd(&out[base + j], accA);
                if (j + 1 < n) atomicAdd(&out[base + j + 1], accB);
                if (j + 2 < n) atomicAdd(&out[base + j + 2], accC);
                if (j + 3 < n) atomicAdd(&out[base + j + 3], accD);
            }
        }
    }
}

// ---------------- host launcher ----------------
extern "C" void kernel_launch(void* const* d_in, const int* in_sizes, int n_in,
                              void* d_out, int out_size)
{
    const int* words      = (const int*)d_in[0];
    const int* tags       = (const int*)d_in[1];
    const int* arc_head   = (const int*)d_in[2];
    const int* arc_mod    = (const int*)d_in[3];
    const int* sib_head   = (const int*)d_in[4];
    const int* sib_mod    = (const int*)d_in[5];
    const int* sib_sib    = (const int*)d_in[6];
    const int* gp_head    = (const int*)d_in[7];
    const int* gp_mod     = (const int*)d_in[8];
    const int* gp_grand   = (const int*)d_in[9];
    const int* gsib_head  = (const int*)d_in[10];
    const int* gsib_mod   = (const int*)d_in[11];
    const int* gsib_sib   = (const int*)d_in[12];
    const int* gsib_grand = (const int*)d_in[13];
    const float* word_emb = (const float*)d_in[14];
    const float* tag_emb  = (const float*)d_in[15];
    const float* Wih_f    = (const float*)d_in[16];
    const float* Whh_f    = (const float*)d_in[17];
    const float* b_f      = (const float*)d_in[18];
    const float* Wih_b    = (const float*)d_in[19];
    const float* Whh_b    = (const float*)d_in[20];
    const float* b_b      = (const float*)d_in[21];
    const float* W_proj   = (const float*)d_in[22];
    const float* W_score  = (const float*)d_in[23];
    const float* null_sib = (const float*)d_in[24];
    float* out = (float*)d_out;

    const int smem_proj = 16 * 2 * H * (int)sizeof(float);            // 51.2 KB
    const int smem2 = (2 * TABROWS * 104 + 104) * (int)sizeof(float); // ~214 KB
    const int smem3 = (3 * TABROWS * 72 + 72) * (int)sizeof(float);   // ~222 KB
    const int smem4 = (4 * TABROWS * 56 + 56) * (int)sizeof(float);   // ~230 KB

    cudaFuncSetAttribute(proj_kernel, cudaFuncAttributeMaxDynamicSharedMemorySize, smem_proj);
    cudaFuncSetAttribute(score_kernel<2>, cudaFuncAttributeMaxDynamicSharedMemorySize, smem2);
    cudaFuncSetAttribute(score_kernel<3>, cudaFuncAttributeMaxDynamicSharedMemorySize, smem3);
    cudaFuncSetAttribute(score_kernel<4>, cudaFuncAttributeMaxDynamicSharedMemorySize, smem4);

    setup_kernel<<<(OUT_TOTAL + 511) / 512, 512>>>(out, OUT_TOTAL);
    zin_kernel<<<SEQ / 4, 256>>>(words, tags, word_emb, tag_emb,
                                 Wih_f, b_f, Wih_b, b_b);
    lstm_kernel<<<2 * LCTA, LTHREADS>>>(Whh_f, Whh_b);
    proj_kernel<<<dim3(12, 16), 256, smem_proj>>>(W_proj, null_sib);

    score_kernel<2><<<dim3(2, 74), 512, smem2>>>(
        0, 1, 0, 0, arc_head, arc_mod, nullptr, nullptr,
        W_score + 0 * M, out, N_ARC, 104);
    score_kernel<3><<<dim3(3, 49), 512, smem3>>>(
        5, 6, 7, 0, sib_head, sib_mod, sib_sib, nullptr,
        W_score + 1 * M, out + N_ARC, N_SIB, 72);
    score_kernel<3><<<dim3(3, 49), 512, smem3>>>(
        3, 4, 2, 0, gp_head, gp_mod, gp_grand, nullptr,
        W_score + 2 * M, out + N_ARC + N_SIB, N_GP, 72);
    score_kernel<4><<<dim3(4, 37), 512, smem4>>>(
        8, 9, 10, 11, gsib_head, gsib_mod, gsib_sib, gsib_grand,
        W_score + 3 * M, out + N_ARC + N_SIB + N_GP, N_GSIB, 56);
}

// round 7
// speedup vs baseline: 2.4935x; 1.0465x over previous
#include <cuda_runtime.h>
#include <math.h>

#define SEQ 256
#define WE 100
#define TE 20
#define INDIM 120
#define H 400
#define G4 1600
#define M 200
#define TABROWS 257
#define N_ARC 65536
#define N_SIB 200000
#define N_GP 200000
#define N_GSIB 300000
#define OUT_TOTAL (N_ARC + N_SIB + N_GP + N_GSIB)

// LSTM decomposition: 20 CTAs per direction, 20 h-units each
#define LCTA 20
#define JH 20
#define LROWS 80
#define LTHREADS 320

// ---------------- device scratch ----------------
__device__ float g_zin[2][SEQ][G4];
__device__ float g_states[SEQ][2 * H];
__device__ float g_tab[12][TABROWS][M];
__device__ float g_h[2][2][H];
__device__ unsigned int g_bar[2];

// ---------------- fast transcendentals (rel err ~1e-6, safe at +-inf) ----
__device__ __forceinline__ float ftanh(float x) {
    float e = __expf(2.f * x);
    return 1.f - __fdividef(2.f, e + 1.f);
}
__device__ __forceinline__ float fsig(float x) {
    return __fdividef(1.f, 1.f + __expf(-x));
}

// ---------------- kernel 0 ----------------
__global__ void setup_kernel(float* __restrict__ out, int n) {
    int i = blockIdx.x * blockDim.x + threadIdx.x;
    if (i < n) out[i] = 0.f;
    if (i < 2) g_bar[i] = 0u;
}

// ---------------- kernel 1: embeddings + z_in ----------------
__global__ void __launch_bounds__(256) zin_kernel(
    const int* __restrict__ words, const int* __restrict__ tags,
    const float* __restrict__ word_emb, const float* __restrict__ tag_emb,
    const float* __restrict__ Wih_f, const float* __restrict__ b_f,
    const float* __restrict__ Wih_b, const float* __restrict__ b_b)
{
    __shared__ __align__(16) float xs[4][INDIM];
    int tid = threadIdx.x;
    int s_base = blockIdx.x * 4;
    int dirr = blockIdx.y;

    for (int i = tid; i < 4 * INDIM; i += 256) {
        int jj = i / INDIM;
        int k = i - jj * INDIM;
        int s = s_base + jj;
        int pos = dirr ? (SEQ - 1 - s) : s;
        float v = (k < WE) ? word_emb[words[pos] * WE + k]
                           : tag_emb[tags[pos] * TE + (k - WE)];
        xs[jj][k] = v;
    }
    __syncthreads();

    const float* Wp = dirr ? Wih_b : Wih_f;
    const float* bp = dirr ? b_b : b_f;
    for (int row = tid; row < G4; row += 256) {
        float bias = bp[row];
        const float4* wr = (const float4*)(Wp + row * INDIM);
        float a0 = 0.f, a1 = 0.f, a2 = 0.f, a3 = 0.f;
        #pragma unroll
        for (int k = 0; k < INDIM / 4; k++) {
            float4 w = __ldg(wr + k);
            const float* x0 = &xs[0][k * 4];
            const float* x1 = &xs[1][k * 4];
            const float* x2 = &xs[2][k * 4];
            const float* x3 = &xs[3][k * 4];
            a0 += w.x * x0[0] + w.y * x0[1] + w.z * x0[2] + w.w * x0[3];
            a1 += w.x * x1[0] + w.y * x1[1] + w.z * x1[2] + w.w * x1[3];
            a2 += w.x * x2[0] + w.y * x2[1] + w.z * x2[2] + w.w * x2[3];
            a3 += w.x * x3[0] + w.y * x3[1] + w.z * x3[2] + w.w * x3[3];
        }
        g_zin[dirr][s_base + 0][row] = a0 + bias;
        g_zin[dirr][s_base + 1][row] = a1 + bias;
        g_zin[dirr][s_base + 2][row] = a2 + bias;
        g_zin[dirr][s_base + 3][row] = a3 + bias;
    }
}

// ---------------- kernel 2: BiLSTM scan (unchanged from R5) ----------------
__global__ void __launch_bounds__(LTHREADS, 1) lstm_kernel(
    const float* __restrict__ Whh_f, const float* __restrict__ Whh_b)
{
    __shared__ __align__(16) float h_sm[H];
    __shared__ float z_sm[LROWS];
    __shared__ float c_sm[JH];

    int dir = blockIdx.x / LCTA;
    int slice = blockIdx.x - dir * LCTA;
    int j0 = slice * JH;
    const float* Whh = dir ? Whh_b : Whh_f;
    int tid = threadIdx.x;
    int r = tid >> 2, q = tid & 3;

    float4 w[25];
    {
        int gate = r / JH, jj = r - gate * JH;
        const float4* wrow = (const float4*)(Whh + (gate * H + j0 + jj) * H + q * 100);
        #pragma unroll
        for (int k = 0; k < 25; k++) w[k] = __ldg(wrow + k);
    }

    for (int i = tid; i < H; i += LTHREADS) h_sm[i] = 0.f;
    if (tid < JH) c_sm[tid] = 0.f;
    __syncthreads();

    const float4* hp = (const float4*)(h_sm + q * 100);
    unsigned int target = LCTA;

    for (int step = 0; step < SEQ; step++) {
        float pz_i = 0.f, pz_f = 0.f, pz_g = 0.f, pz_o = 0.f;
        if (tid < JH) {
            const float* zin = &g_zin[dir][step][0];
            pz_i = __ldg(zin + 0 * H + j0 + tid);
            pz_f = __ldg(zin + 1 * H + j0 + tid);
            pz_g = __ldg(zin + 2 * H + j0 + tid);
            pz_o = __ldg(zin + 3 * H + j0 + tid);
        }

        float a0 = 0.f, a1 = 0.f, a2 = 0.f, a3 = 0.f;
        #pragma unroll
        for (int k = 0; k < 24; k += 4) {
            float4 h0 = hp[k],     h1 = hp[k + 1];
            float4 h2 = hp[k + 2], h3 = hp[k + 3];
            a0 += w[k].x * h0.x + w[k].y * h0.y + w[k].z * h0.z + w[k].w * h0.w;
            a1 += w[k+1].x * h1.x + w[k+1].y * h1.y + w[k+1].z * h1.z + w[k+1].w * h1.w;
            a2 += w[k+2].x * h2.x + w[k+2].y * h2.y + w[k+2].z * h2.z + w[k+2].w * h2.w;
            a3 += w[k+3].x * h3.x + w[k+3].y * h3.y + w[k+3].z * h3.z + w[k+3].w * h3.w;
        }
        {
            float4 h24 = hp[24];
            a0 += w[24].x * h24.x + w[24].y * h24.y + w[24].z * h24.z + w[24].w * h24.w;
        }
        float acc = (a0 + a1) + (a2 + a3);
        acc += __shfl_down_sync(0xffffffffu, acc, 2, 4);
        acc += __shfl_down_sync(0xffffffffu, acc, 1, 4);
        if (q == 0) z_sm[r] = acc;
        __syncthreads();

        if (tid < JH) {
            float zi = z_sm[tid]           + pz_i;
            float zf = z_sm[JH + tid]      + pz_f;
            float zg = z_sm[2 * JH + tid]  + pz_g;
            float zo = z_sm[3 * JH + tid]  + pz_o;
            float ig = fsig(zi), fg = fsig(zf), og = fsig(zo);
            float gg = ftanh(zg);
            float c = fg * c_sm[tid] + ig * gg;
            c_sm[tid] = c;
            float h = og * ftanh(c);
            __stcg(&g_h[(step + 1) & 1][dir][j0 + tid], h);
            int tpos = dir ? (SEQ - 1 - step) : step;
            g_states[tpos][dir * H + j0 + tid] = h;
        }
        __syncthreads();

        if (tid == 0) {
            asm volatile("red.release.gpu.global.add.u32 [%0], 1;"
                         :: "l"(&g_bar[dir]) : "memory");
            unsigned int v;
            do {
                asm volatile("ld.acquire.gpu.global.u32 %0, [%1];"
                             : "=r"(v) : "l"(&g_bar[dir]) : "memory");
            } while (v < target);
        }
        __syncthreads();
        target += LCTA;

        if (step < SEQ - 1) {
            if (tid < 100)
                *(float4*)(h_sm + tid * 4) =
                    __ldcg((const float4*)&g_h[(step + 1) & 1][dir][tid * 4]);
            __syncthreads();
        }
    }
}

// ---------------- kernel 3: projection (unroll 4 for MLP) ----------------
__global__ void __launch_bounds__(256) proj_kernel(
    const float* __restrict__ W_proj, const float* __restrict__ null_sib)
{
    extern __shared__ float st[];              // [16][800]
    int p = blockIdx.x;
    int s0 = blockIdx.y * 16;
    int tid = threadIdx.x;
    for (int i = tid; i < 16 * 2 * H; i += 256)
        st[i] = g_states[s0 + i / (2 * H)][i % (2 * H)];
    __syncthreads();

    if (tid < M) {
        float acc[16];
        #pragma unroll
        for (int s = 0; s < 16; s++) acc[s] = 0.f;
        const float4* w = (const float4*)(W_proj + ((size_t)p * M + tid) * 2 * H);
        #pragma unroll 4
        for (int k = 0; k < (2 * H) / 4; k++) {
            float4 wv = __ldg(w + k);
            #pragma unroll
            for (int s = 0; s < 16; s++) {
                float4 sv = *(const float4*)&st[s * 2 * H + k * 4];
                acc[s] += wv.x * sv.x + wv.y * sv.y + wv.z * sv.z + wv.w * sv.w;
            }
        }
        #pragma unroll
        for (int s = 0; s < 16; s++)
            g_tab[p][s0 + s][tid] = acc[s];
        if ((p == 7 || p == 10) && blockIdx.y == 0)
            g_tab[p][256][tid] = null_sib[tid];
    }
}

// ---------------- kernel 4: scoring ----------------
// One launch per m-chunk. T tables, R rows, MC columns (chunk [m0, m0+MC)),
// KI = ceil(MC/32) k-iters, fully unrolled. ws chunk in registers, zeroed
// past valid columns so tail-iteration garbage reads contribute exactly 0
// (smem padded +64 floats to keep them in-bounds). N % 32 == 0 by data.
template <int T, int R, int MC, int KI>
__global__ void __launch_bounds__(512) score_kernel(
    int p0, int p1, int p2, int p3, int m0,
    const int* __restrict__ i0, const int* __restrict__ i1,
    const int* __restrict__ i2, const int* __restrict__ i3,
    const float* __restrict__ ws, float* __restrict__ out, int N)
{
    extern __shared__ float smem[];

    // stage tables
    int pp[4] = {p0, p1, p2, p3};
    #pragma unroll
    for (int t = 0; t < T; t++) {
        const float* src = &g_tab[pp[t]][0][0];
        float* dst = smem + t * R * MC;
        for (int i = threadIdx.x; i < R * MC; i += 512) {
            int s = i / MC, mm = i - s * MC;
            dst[i] = __ldg(src + s * M + m0 + mm);
        }
    }
    int lane = threadIdx.x & 31;
    float wsr[KI];
    #pragma unroll
    for (int k = 0; k < KI; k++) {
        int mi = k * 32 + lane;
        wsr[k] = (mi < MC && m0 + mi < M) ? __ldg(ws + m0 + mi) : 0.f;
    }
    __syncthreads();

    const float* T0 = smem;
    const float* T1 = smem + R * MC;
    const float* T2 = smem + 2 * R * MC;
    const float* T3 = smem + 3 * R * MC;

    int wid = threadIdx.x >> 5;
    int gw = blockIdx.x * 16 + wid;
    const int stride = gridDim.x * 16 * 32;

    for (int base = gw * 32; base < N; base += stride) {
        int a0 = i0[base + lane];
        int a1 = i1[base + lane];
        int a2 = (T > 2) ? i2[base + lane] : 0;
        int a3 = (T > 3) ? i3[base + lane] : 0;

        #pragma unroll
        for (int j = 0; j < 32; j += 4) {
            const float *h_[4], *m_[4], *s_[4], *g_[4];
            #pragma unroll
            for (int u = 0; u < 4; u++) {
                h_[u] = T0 + __shfl_sync(0xffffffffu, a0, j + u) * MC;
                m_[u] = T1 + __shfl_sync(0xffffffffu, a1, j + u) * MC;
                if (T > 2) s_[u] = T2 + __shfl_sync(0xffffffffu, a2, j + u) * MC;
                if (T > 3) g_[u] = T3 + __shfl_sync(0xffffffffu, a3, j + u) * MC;
            }
            float acc[4] = {0.f, 0.f, 0.f, 0.f};
            #pragma unroll
            for (int k = 0; k < KI; k++) {
                int mm = k * 32 + lane;
                #pragma unroll
                for (int u = 0; u < 4; u++) {
                    float v = h_[u][mm] + m_[u][mm];
                    if (T > 2) v += s_[u][mm];
                    if (T > 3) v += g_[u][mm];
                    acc[u] += wsr[k] * ftanh(v);
                }
            }
            #pragma unroll
            for (int off = 16; off; off >>= 1) {
                #pragma unroll
                for (int u = 0; u < 4; u++)
                    acc[u] += __shfl_xor_sync(0xffffffffu, acc[u], off);
            }
            if (lane < 4) atomicAdd(&out[base + j + lane], acc[lane]);
        }
    }
}

// ---------------- host launcher ----------------
template <int T, int R, int MC, int KI>
static void launch_score(int p0, int p1, int p2, int p3, int m0,
                         const int* i0, const int* i1, const int* i2, const int* i3,
                         const float* ws, float* out, int N)
{
    const int smem = (T * R * MC + 64) * (int)sizeof(float);
    cudaFuncSetAttribute(score_kernel<T, R, MC, KI>,
                         cudaFuncAttributeMaxDynamicSharedMemorySize, smem);
    score_kernel<T, R, MC, KI><<<148, 512, smem>>>(
        p0, p1, p2, p3, m0, i0, i1, i2, i3, ws, out, N);
}

extern "C" void kernel_launch(void* const* d_in, const int* in_sizes, int n_in,
                              void* d_out, int out_size)
{
    const int* words      = (const int*)d_in[0];
    const int* tags       = (const int*)d_in[1];
    const int* arc_head   = (const int*)d_in[2];
    const int* arc_mod    = (const int*)d_in[3];
    const int* sib_head   = (const int*)d_in[4];
    const int* sib_mod    = (const int*)d_in[5];
    const int* sib_sib    = (const int*)d_in[6];
    const int* gp_head    = (const int*)d_in[7];
    const int* gp_mod     = (const int*)d_in[8];
    const int* gp_grand   = (const int*)d_in[9];
    const int* gsib_head  = (const int*)d_in[10];
    const int* gsib_mod   = (const int*)d_in[11];
    const int* gsib_sib   = (const int*)d_in[12];
    const int* gsib_grand = (const int*)d_in[13];
    const float* word_emb = (const float*)d_in[14];
    const float* tag_emb  = (const float*)d_in[15];
    const float* Wih_f    = (const float*)d_in[16];
    const float* Whh_f    = (const float*)d_in[17];
    const float* b_f      = (const float*)d_in[18];
    const float* Wih_b    = (const float*)d_in[19];
    const float* Whh_b    = (const float*)d_in[20];
    const float* b_b      = (const float*)d_in[21];
    const float* W_proj   = (const float*)d_in[22];
    const float* W_score  = (const float*)d_in[23];
    const float* null_sib = (const float*)d_in[24];
    float* out = (float*)d_out;

    const int smem_proj = 16 * 2 * H * (int)sizeof(float);
    cudaFuncSetAttribute(proj_kernel, cudaFuncAttributeMaxDynamicSharedMemorySize, smem_proj);

    setup_kernel<<<(OUT_TOTAL + 511) / 512, 512>>>(out, OUT_TOTAL);
    zin_kernel<<<dim3(SEQ / 4, 2), 256>>>(words, tags, word_emb, tag_emb,
                                          Wih_f, b_f, Wih_b, b_b);
    lstm_kernel<<<2 * LCTA, LTHREADS>>>(Whh_f, Whh_b);
    proj_kernel<<<dim3(12, 16), 256, smem_proj>>>(W_proj, null_sib);

    const float* ws_arc  = W_score + 0 * M;
    const float* ws_sib  = W_score + 1 * M;
    const float* ws_gp   = W_score + 2 * M;
    const float* ws_gsib = W_score + 3 * M;
    float* o_arc  = out;
    float* o_sib  = out + N_ARC;
    float* o_gp   = out + N_ARC + N_SIB;
    float* o_gsib = out + N_ARC + N_SIB + N_GP;

    // arc: T=2, 256 rows, chunks {104, 96}
    launch_score<2, 256, 104, 4>(0, 1, 0, 0, 0,   arc_head, arc_mod, 0, 0, ws_arc, o_arc, N_ARC);
    launch_score<2, 256,  96, 3>(0, 1, 0, 0, 104, arc_head, arc_mod, 0, 0, ws_arc, o_arc, N_ARC);
    // sib: T=3, 257 rows, chunks {72, 72, 56}
    launch_score<3, 257, 72, 3>(5, 6, 7, 0, 0,   sib_head, sib_mod, sib_sib, 0, ws_sib, o_sib, N_SIB);
    launch_score<3, 257, 72, 3>(5, 6, 7, 0, 72,  sib_head, sib_mod, sib_sib, 0, ws_sib, o_sib, N_SIB);
    launch_score<3, 257, 56, 2>(5, 6, 7, 0, 144, sib_head, sib_mod, sib_sib, 0, ws_sib, o_sib, N_SIB);
    // gp: T=3, 257 rows (g tables have 256 valid rows; indices < 256), chunks {72, 72, 56}
    launch_score<3, 257, 72, 3>(3, 4, 2, 0, 0,   gp_head, gp_mod, gp_grand, 0, ws_gp, o_gp, N_GP);
    launch_score<3, 257, 72, 3>(3, 4, 2, 0, 72,  gp_head, gp_mod, gp_grand, 0, ws_gp, o_gp, N_GP);
    launch_score<3, 257, 56, 2>(3, 4, 2, 0, 144, gp_head, gp_mod, gp_grand, 0, ws_gp, o_gp, N_GP);
    // gsib: T=4, 257 rows, chunks {56, 56, 56, 32}
    launch_score<4, 257, 56, 2>(8, 9, 10, 11, 0,   gsib_head, gsib_mod, gsib_sib, gsib_grand, ws_gsib, o_gsib, N_GSIB);
    launch_score<4, 257, 56, 2>(8, 9, 10, 11, 56,  gsib_head, gsib_mod, gsib_sib, gsib_grand, ws_gsib, o_gsib, N_GSIB);
    launch_score<4, 257, 56, 2>(8, 9, 10, 11, 112, gsib_head, gsib_mod, gsib_sib, gsib_grand, ws_gsib, o_gsib, N_GSIB);
    launch_score<4, 257, 32, 1>(8, 9, 10, 11, 168, gsib_head, gsib_mod, gsib_sib, gsib_grand, ws_gsib, o_gsib, N_GSIB);
}

// round 8
// speedup vs baseline: 2.7552x; 1.1049x over previous
#include <cuda_runtime.h>
#include <math.h>

#define SEQ 256
#define WE 100
#define TE 20
#define INDIM 120
#define H 400
#define G4 1600
#define M 200
#define TABROWS 257
#define N_ARC 65536
#define N_SIB 200000
#define N_GP 200000
#define N_GSIB 300000
#define OUT_TOTAL (N_ARC + N_SIB + N_GP + N_GSIB)

// LSTM decomposition: 40 CTAs per direction, 10 h-units each
#define LCTA 40
#define JH 10
#define LROWS 40          // 4 gates * 10
#define LTHREADS 160      // 4 threads per row

#define SCORE_THREADS 768

// ---------------- device scratch ----------------
__device__ float g_zin[2][SEQ][G4];
__device__ float g_states[SEQ][2 * H];
__device__ float g_tab[12][TABROWS][M];
__device__ float g_h[2][2][H];
__device__ unsigned int g_bar[2];

// ---------------- fast transcendentals (rel err ~1e-6, safe at +-inf) ----
__device__ __forceinline__ float ftanh(float x) {
    float e = __expf(2.f * x);
    return 1.f - __fdividef(2.f, e + 1.f);
}
__device__ __forceinline__ float fsig(float x) {
    return __fdividef(1.f, 1.f + __expf(-x));
}

// ---------------- kernel 0 ----------------
__global__ void setup_kernel(float* __restrict__ out, int n) {
    int i = blockIdx.x * blockDim.x + threadIdx.x;
    if (i < n) out[i] = 0.f;
    if (i < 2) g_bar[i] = 0u;
}

// ---------------- kernel 1: embeddings + z_in ----------------
__global__ void __launch_bounds__(256) zin_kernel(
    const int* __restrict__ words, const int* __restrict__ tags,
    const float* __restrict__ word_emb, const float* __restrict__ tag_emb,
    const float* __restrict__ Wih_f, const float* __restrict__ b_f,
    const float* __restrict__ Wih_b, const float* __restrict__ b_b)
{
    __shared__ __align__(16) float xs[4][INDIM];
    int tid = threadIdx.x;
    int s_base = blockIdx.x * 4;
    int dirr = blockIdx.y;

    for (int i = tid; i < 4 * INDIM; i += 256) {
        int jj = i / INDIM;
        int k = i - jj * INDIM;
        int s = s_base + jj;
        int pos = dirr ? (SEQ - 1 - s) : s;
        float v = (k < WE) ? word_emb[words[pos] * WE + k]
                           : tag_emb[tags[pos] * TE + (k - WE)];
        xs[jj][k] = v;
    }
    __syncthreads();

    const float* Wp = dirr ? Wih_b : Wih_f;
    const float* bp = dirr ? b_b : b_f;
    for (int row = tid; row < G4; row += 256) {
        float bias = bp[row];
        const float4* wr = (const float4*)(Wp + row * INDIM);
        float a0 = 0.f, a1 = 0.f, a2 = 0.f, a3 = 0.f;
        #pragma unroll
        for (int k = 0; k < INDIM / 4; k++) {
            float4 w = __ldg(wr + k);
            const float* x0 = &xs[0][k * 4];
            const float* x1 = &xs[1][k * 4];
            const float* x2 = &xs[2][k * 4];
            const float* x3 = &xs[3][k * 4];
            a0 += w.x * x0[0] + w.y * x0[1] + w.z * x0[2] + w.w * x0[3];
            a1 += w.x * x1[0] + w.y * x1[1] + w.z * x1[2] + w.w * x1[3];
            a2 += w.x * x2[0] + w.y * x2[1] + w.z * x2[2] + w.w * x2[3];
            a3 += w.x * x3[0] + w.y * x3[1] + w.z * x3[2] + w.w * x3[3];
        }
        g_zin[dirr][s_base + 0][row] = a0 + bias;
        g_zin[dirr][s_base + 1][row] = a1 + bias;
        g_zin[dirr][s_base + 2][row] = a2 + bias;
        g_zin[dirr][s_base + 3][row] = a3 + bias;
    }
}

// ---------------- kernel 2: BiLSTM scan, 40 CTAs per direction ----------------
// Thread (r,q): r in [0,40) gate-row, q in [0,4); 100 weight floats in regs.
__global__ void __launch_bounds__(LTHREADS, 1) lstm_kernel(
    const float* __restrict__ Whh_f, const float* __restrict__ Whh_b)
{
    __shared__ __align__(16) float h_sm[H];
    __shared__ float z_sm[LROWS];
    __shared__ float c_sm[JH];

    int dir = blockIdx.x / LCTA;
    int slice = blockIdx.x - dir * LCTA;
    int j0 = slice * JH;
    const float* Whh = dir ? Whh_b : Whh_f;
    int tid = threadIdx.x;
    int r = tid >> 2, q = tid & 3;

    float4 w[25];
    {
        int gate = r / JH, jj = r - gate * JH;
        const float4* wrow = (const float4*)(Whh + (gate * H + j0 + jj) * H + q * 100);
        #pragma unroll
        for (int k = 0; k < 25; k++) w[k] = __ldg(wrow + k);
    }

    for (int i = tid; i < H; i += LTHREADS) h_sm[i] = 0.f;
    if (tid < JH) c_sm[tid] = 0.f;
    __syncthreads();

    const float4* hp = (const float4*)(h_sm + q * 100);
    unsigned int target = LCTA;

    for (int step = 0; step < SEQ; step++) {
        float pz_i = 0.f, pz_f = 0.f, pz_g = 0.f, pz_o = 0.f;
        if (tid < JH) {
            const float* zin = &g_zin[dir][step][0];
            pz_i = __ldg(zin + 0 * H + j0 + tid);
            pz_f = __ldg(zin + 1 * H + j0 + tid);
            pz_g = __ldg(zin + 2 * H + j0 + tid);
            pz_o = __ldg(zin + 3 * H + j0 + tid);
        }

        float a0 = 0.f, a1 = 0.f, a2 = 0.f, a3 = 0.f;
        #pragma unroll
        for (int k = 0; k < 24; k += 4) {
            float4 h0 = hp[k],     h1 = hp[k + 1];
            float4 h2 = hp[k + 2], h3 = hp[k + 3];
            a0 += w[k].x * h0.x + w[k].y * h0.y + w[k].z * h0.z + w[k].w * h0.w;
            a1 += w[k+1].x * h1.x + w[k+1].y * h1.y + w[k+1].z * h1.z + w[k+1].w * h1.w;
            a2 += w[k+2].x * h2.x + w[k+2].y * h2.y + w[k+2].z * h2.z + w[k+2].w * h2.w;
            a3 += w[k+3].x * h3.x + w[k+3].y * h3.y + w[k+3].z * h3.z + w[k+3].w * h3.w;
        }
        {
            float4 h24 = hp[24];
            a0 += w[24].x * h24.x + w[24].y * h24.y + w[24].z * h24.z + w[24].w * h24.w;
        }
        float acc = (a0 + a1) + (a2 + a3);
        acc += __shfl_down_sync(0xffffffffu, acc, 2, 4);
        acc += __shfl_down_sync(0xffffffffu, acc, 1, 4);
        if (q == 0) z_sm[r] = acc;
        __syncthreads();

        if (tid < JH) {
            float zi = z_sm[tid]           + pz_i;
            float zf = z_sm[JH + tid]      + pz_f;
            float zg = z_sm[2 * JH + tid]  + pz_g;
            float zo = z_sm[3 * JH + tid]  + pz_o;
            float ig = fsig(zi), fg = fsig(zf), og = fsig(zo);
            float gg = ftanh(zg);
            float c = fg * c_sm[tid] + ig * gg;
            c_sm[tid] = c;
            float h = og * ftanh(c);
            __stcg(&g_h[(step + 1) & 1][dir][j0 + tid], h);
            int tpos = dir ? (SEQ - 1 - step) : step;
            g_states[tpos][dir * H + j0 + tid] = h;
        }
        __syncthreads();

        if (tid == 0) {
            asm volatile("red.release.gpu.global.add.u32 [%0], 1;"
                         :: "l"(&g_bar[dir]) : "memory");
            unsigned int v;
            do {
                asm volatile("ld.acquire.gpu.global.u32 %0, [%1];"
                             : "=r"(v) : "l"(&g_bar[dir]) : "memory");
            } while (v < target);
        }
        __syncthreads();
        target += LCTA;

        if (step < SEQ - 1) {
            if (tid < 100)
                *(float4*)(h_sm + tid * 4) =
                    __ldcg((const float4*)&g_h[(step + 1) & 1][dir][tid * 4]);
            __syncthreads();
        }
    }
}

// ---------------- kernel 3: projection, 8-way batched loads ----------------
__global__ void __launch_bounds__(256) proj_kernel(
    const float* __restrict__ W_proj, const float* __restrict__ null_sib)
{
    extern __shared__ float st[];              // [16][800]
    int p = blockIdx.x;
    int s0 = blockIdx.y * 16;
    int tid = threadIdx.x;
    for (int i = tid; i < 16 * 2 * H; i += 256)
        st[i] = g_states[s0 + i / (2 * H)][i % (2 * H)];
    __syncthreads();

    if (tid < M) {
        float acc[16];
        #pragma unroll
        for (int s = 0; s < 16; s++) acc[s] = 0.f;
        const float4* w = (const float4*)(W_proj + ((size_t)p * M + tid) * 2 * H);
        for (int k0 = 0; k0 < (2 * H) / 4; k0 += 8) {
            float4 wv[8];
            #pragma unroll
            for (int j = 0; j < 8; j++) wv[j] = __ldg(w + k0 + j);  // 8 in flight
            #pragma unroll
            for (int j = 0; j < 8; j++) {
                #pragma unroll
                for (int s = 0; s < 16; s++) {
                    float4 sv = *(const float4*)&st[s * 2 * H + (k0 + j) * 4];
                    acc[s] += wv[j].x * sv.x + wv[j].y * sv.y
                            + wv[j].z * sv.z + wv[j].w * sv.w;
                }
            }
        }
        #pragma unroll
        for (int s = 0; s < 16; s++)
            g_tab[p][s0 + s][tid] = acc[s];
        if ((p == 7 || p == 10) && blockIdx.y == 0)
            g_tab[p][256][tid] = null_sib[tid];
    }
}

// ---------------- kernel 4: scoring ----------------
// One launch per m-chunk. ws chunk in registers, zeroed past valid columns so
// tail-iteration garbage reads contribute exactly 0 (smem padded in-bounds).
template <int T, int R, int MC, int KI>
__global__ void __launch_bounds__(SCORE_THREADS) score_kernel(
    int p0, int p1, int p2, int p3, int m0,
    const int* __restrict__ i0, const int* __restrict__ i1,
    const int* __restrict__ i2, const int* __restrict__ i3,
    const float* __restrict__ ws, float* __restrict__ out, int N)
{
    extern __shared__ float smem[];

    int pp[4] = {p0, p1, p2, p3};
    #pragma unroll
    for (int t = 0; t < T; t++) {
        const float* src = &g_tab[pp[t]][0][0];
        float* dst = smem + t * R * MC;
        for (int i = threadIdx.x; i < R * MC; i += SCORE_THREADS) {
            int s = i / MC, mm = i - s * MC;
            dst[i] = __ldg(src + s * M + m0 + mm);
        }
    }
    int lane = threadIdx.x & 31;
    float wsr[KI];
    #pragma unroll
    for (int k = 0; k < KI; k++) {
        int mi = k * 32 + lane;
        wsr[k] = (mi < MC && m0 + mi < M) ? __ldg(ws + m0 + mi) : 0.f;
    }
    __syncthreads();

    const float* T0 = smem;
    const float* T1 = smem + R * MC;
    const float* T2 = smem + 2 * R * MC;
    const float* T3 = smem + 3 * R * MC;

    int wid = threadIdx.x >> 5;
    int gw = blockIdx.x * (SCORE_THREADS / 32) + wid;
    const int stride = gridDim.x * (SCORE_THREADS / 32) * 32;

    for (int base = gw * 32; base < N; base += stride) {
        int a0 = i0[base + lane];
        int a1 = i1[base + lane];
        int a2 = (T > 2) ? i2[base + lane] : 0;
        int a3 = (T > 3) ? i3[base + lane] : 0;

        #pragma unroll
        for (int j = 0; j < 32; j += 4) {
            const float *h_[4], *m_[4], *s_[4], *g_[4];
            #pragma unroll
            for (int u = 0; u < 4; u++) {
                h_[u] = T0 + __shfl_sync(0xffffffffu, a0, j + u) * MC;
                m_[u] = T1 + __shfl_sync(0xffffffffu, a1, j + u) * MC;
                if (T > 2) s_[u] = T2 + __shfl_sync(0xffffffffu, a2, j + u) * MC;
                if (T > 3) g_[u] = T3 + __shfl_sync(0xffffffffu, a3, j + u) * MC;
            }
            float acc[4] = {0.f, 0.f, 0.f, 0.f};
            #pragma unroll
            for (int k = 0; k < KI; k++) {
                int mm = k * 32 + lane;
                #pragma unroll
                for (int u = 0; u < 4; u++) {
                    float v = h_[u][mm] + m_[u][mm];
                    if (T > 2) v += s_[u][mm];
                    if (T > 3) v += g_[u][mm];
                    acc[u] += wsr[k] * ftanh(v);
                }
            }
            #pragma unroll
            for (int off = 16; off; off >>= 1) {
                #pragma unroll
                for (int u = 0; u < 4; u++)
                    acc[u] += __shfl_xor_sync(0xffffffffu, acc[u], off);
            }
            if (lane < 4) atomicAdd(&out[base + j + lane], acc[lane]);
        }
    }
}

// ---------------- host launcher ----------------
template <int T, int R, int MC, int KI>
static void launch_score(int p0, int p1, int p2, int p3, int m0,
                         const int* i0, const int* i1, const int* i2, const int* i3,
                         const float* ws, float* out, int N)
{
    const int smem = (T * R * MC + 64) * (int)sizeof(float);
    cudaFuncSetAttribute(score_kernel<T, R, MC, KI>,
                         cudaFuncAttributeMaxDynamicSharedMemorySize, smem);
    score_kernel<T, R, MC, KI><<<148, SCORE_THREADS, smem>>>(
        p0, p1, p2, p3, m0, i0, i1, i2, i3, ws, out, N);
}

extern "C" void kernel_launch(void* const* d_in, const int* in_sizes, int n_in,
                              void* d_out, int out_size)
{
    const int* words      = (const int*)d_in[0];
    const int* tags       = (const int*)d_in[1];
    const int* arc_head   = (const int*)d_in[2];
    const int* arc_mod    = (const int*)d_in[3];
    const int* sib_head   = (const int*)d_in[4];
    const int* sib_mod    = (const int*)d_in[5];
    const int* sib_sib    = (const int*)d_in[6];
    const int* gp_head    = (const int*)d_in[7];
    const int* gp_mod     = (const int*)d_in[8];
    const int* gp_grand   = (const int*)d_in[9];
    const int* gsib_head  = (const int*)d_in[10];
    const int* gsib_mod   = (const int*)d_in[11];
    const int* gsib_sib   = (const int*)d_in[12];
    const int* gsib_grand = (const int*)d_in[13];
    const float* word_emb = (const float*)d_in[14];
    const float* tag_emb  = (const float*)d_in[15];
    const float* Wih_f    = (const float*)d_in[16];
    const float* Whh_f    = (const float*)d_in[17];
    const float* b_f      = (const float*)d_in[18];
    const float* Wih_b    = (const float*)d_in[19];
    const float* Whh_b    = (const float*)d_in[20];
    const float* b_b      = (const float*)d_in[21];
    const float* W_proj   = (const float*)d_in[22];
    const float* W_score  = (const float*)d_in[23];
    const float* null_sib = (const float*)d_in[24];
    float* out = (float*)d_out;

    const int smem_proj = 16 * 2 * H * (int)sizeof(float);
    cudaFuncSetAttribute(proj_kernel, cudaFuncAttributeMaxDynamicSharedMemorySize, smem_proj);

    setup_kernel<<<(OUT_TOTAL + 511) / 512, 512>>>(out, OUT_TOTAL);
    zin_kernel<<<dim3(SEQ / 4, 2), 256>>>(words, tags, word_emb, tag_emb,
                                          Wih_f, b_f, Wih_b, b_b);
    lstm_kernel<<<2 * LCTA, LTHREADS>>>(Whh_f, Whh_b);
    proj_kernel<<<dim3(12, 16), 256, smem_proj>>>(W_proj, null_sib);

    const float* ws_arc  = W_score + 0 * M;
    const float* ws_sib  = W_score + 1 * M;
    const float* ws_gp   = W_score + 2 * M;
    const float* ws_gsib = W_score + 3 * M;
    float* o_arc  = out;
    float* o_sib  = out + N_ARC;
    float* o_gp   = out + N_ARC + N_SIB;
    float* o_gsib = out + N_ARC + N_SIB + N_GP;

    launch_score<2, 256, 104, 4>(0, 1, 0, 0, 0,   arc_head, arc_mod, 0, 0, ws_arc, o_arc, N_ARC);
    launch_score<2, 256,  96, 3>(0, 1, 0, 0, 104, arc_head, arc_mod, 0, 0, ws_arc, o_arc, N_ARC);
    launch_score<3, 257, 72, 3>(5, 6, 7, 0, 0,   sib_head, sib_mod, sib_sib, 0, ws_sib, o_sib, N_SIB);
    launch_score<3, 257, 72, 3>(5, 6, 7, 0, 72,  sib_head, sib_mod, sib_sib, 0, ws_sib, o_sib, N_SIB);
    launch_score<3, 257, 56, 2>(5, 6, 7, 0, 144, sib_head, sib_mod, sib_sib, 0, ws_sib, o_sib, N_SIB);
    launch_score<3, 257, 72, 3>(3, 4, 2, 0, 0,   gp_head, gp_mod, gp_grand, 0, ws_gp, o_gp, N_GP);
    launch_score<3, 257, 72, 3>(3, 4, 2, 0, 72,  gp_head, gp_mod, gp_grand, 0, ws_gp, o_gp, N_GP);
    launch_score<3, 257, 56, 2>(3, 4, 2, 0, 144, gp_head, gp_mod, gp_grand, 0, ws_gp, o_gp, N_GP);
    launch_score<4, 257, 56, 2>(8, 9, 10, 11, 0,   gsib_head, gsib_mod, gsib_sib, gsib_grand, ws_gsib, o_gsib, N_GSIB);
    launch_score<4, 257, 56, 2>(8, 9, 10, 11, 56,  gsib_head, gsib_mod, gsib_sib, gsib_grand, ws_gsib, o_gsib, N_GSIB);
    launch_score<4, 257, 56, 2>(8, 9, 10, 11, 112, gsib_head, gsib_mod, gsib_sib, gsib_grand, ws_gsib, o_gsib, N_GSIB);
    launch_score<4, 257, 32, 1>(8, 9, 10, 11, 168, gsib_head, gsib_mod, gsib_sib, gsib_grand, ws_gsib, o_gsib, N_GSIB);
}